// round 9
// baseline (speedup 1.0000x reference)
#include <cuda_runtime.h>
#include <cuda_bf16.h>
#include <math.h>
#include <cstdint>

#define BATCH  8192
#define IN_DIM 4096
#define MEMD   256
#define KDIM   4352
#define NTOT   1024

// gmem scratch
__device__ float         g_Y [(size_t)BATCH * NTOT];
__device__ __nv_bfloat16 g_Ah[(size_t)BATCH * KDIM];
__device__ __nv_bfloat16 g_Al[(size_t)BATCH * KDIM];
__device__ __nv_bfloat16 g_Bh[(size_t)NTOT  * KDIM];
__device__ __nv_bfloat16 g_Bl[(size_t)NTOT  * KDIM];
__device__ float         g_ball[NTOT];

// ------------------------------- helpers ----------------------------------
__device__ __forceinline__ uint32_t smem_u32(const void* p){
    uint32_t a;
    asm("{ .reg .u64 t; cvta.to.shared.u64 t, %1; cvt.u32.u64 %0, t; }" : "=r"(a) : "l"(p));
    return a;
}
__device__ __forceinline__ void splitf(float v, unsigned short& hi, unsigned short& lo){
    __nv_bfloat16 h = __float2bfloat16(v);
    __nv_bfloat16 l = __float2bfloat16(v - __bfloat162float(h));
    hi = __bfloat16_as_ushort(h);
    lo = __bfloat16_as_ushort(l);
}

#define CP_ASYNC16(dst, src) \
    asm volatile("cp.async.cg.shared.global [%0], [%1], 16;" :: "r"(dst), "l"(src))
#define CP_COMMIT() asm volatile("cp.async.commit_group;" ::: "memory")
#define CP_WAIT1()  asm volatile("cp.async.wait_group 1;" ::: "memory")
#define CP_WAIT0()  asm volatile("cp.async.wait_group 0;" ::: "memory")

#define LDSM4(r, addr) \
    asm volatile("ldmatrix.sync.aligned.m8n8.x4.shared.b16 {%0,%1,%2,%3}, [%4];" \
        : "=r"((r)[0]), "=r"((r)[1]), "=r"((r)[2]), "=r"((r)[3]) : "r"(addr))

#define MMA16816(d, a, b0, b1) \
    asm volatile("mma.sync.aligned.m16n8k16.row.col.f32.bf16.bf16.f32 " \
        "{%0,%1,%2,%3}, {%4,%5,%6,%7}, {%8,%9}, {%0,%1,%2,%3};" \
        : "+f"((d)[0]), "+f"((d)[1]), "+f"((d)[2]), "+f"((d)[3]) \
        : "r"((a)[0]), "r"((a)[1]), "r"((a)[2]), "r"((a)[3]), "r"(b0), "r"(b1))

// ---------------------------------------------------------------------------
// Prep A: split [h|x] -> bf16 hi/lo planes, row-major [m][k]
// ---------------------------------------------------------------------------
__global__ __launch_bounds__(256)
void prep_a(const float* __restrict__ x, const float* __restrict__ h)
{
    const int id = blockIdx.x * 256 + threadIdx.x;
    const int m  = id / 544;
    const int k  = (id % 544) * 8;
    const float* src = (k < MEMD) ? h + (size_t)m * MEMD + k
                                  : x + (size_t)m * IN_DIM + (k - MEMD);
    float4 v0 = *reinterpret_cast<const float4*>(src);
    float4 v1 = *reinterpret_cast<const float4*>(src + 4);
    float vv[8] = {v0.x, v0.y, v0.z, v0.w, v1.x, v1.y, v1.z, v1.w};
    unsigned short hs[8], ls[8];
    #pragma unroll
    for (int i = 0; i < 8; i++) splitf(vv[i], hs[i], ls[i]);
    uint4 H, L;
    H.x = hs[0] | ((uint32_t)hs[1] << 16);  H.y = hs[2] | ((uint32_t)hs[3] << 16);
    H.z = hs[4] | ((uint32_t)hs[5] << 16);  H.w = hs[6] | ((uint32_t)hs[7] << 16);
    L.x = ls[0] | ((uint32_t)ls[1] << 16);  L.y = ls[2] | ((uint32_t)ls[3] << 16);
    L.z = ls[4] | ((uint32_t)ls[5] << 16);  L.w = ls[6] | ((uint32_t)ls[7] << 16);
    *reinterpret_cast<uint4*>(g_Ah + (size_t)m * KDIM + k) = H;
    *reinterpret_cast<uint4*>(g_Al + (size_t)m * KDIM + k) = L;
}

// ---------------------------------------------------------------------------
// Prep W: transpose+concat [W1|Wd|Wu] -> bf16 hi/lo planes [n][k]
// ---------------------------------------------------------------------------
__global__ void prep_w(const float* __restrict__ W1, const float* __restrict__ Wd,
                       const float* __restrict__ Wu,
                       const float* __restrict__ b1, const float* __restrict__ bd,
                       const float* __restrict__ bu)
{
    __shared__ float t[32][33];
    const int k0 = blockIdx.x * 32, n0 = blockIdx.y * 32;
    const int tx = threadIdx.x, ty = threadIdx.y;
    const float* Wsrc; int ldw, noff;
    if (n0 < 512)      { Wsrc = W1; ldw = 512; noff = 0; }
    else if (n0 < 768) { Wsrc = Wd; ldw = 256; noff = 512; }
    else               { Wsrc = Wu; ldw = 256; noff = 768; }
    #pragma unroll
    for (int i = 0; i < 4; i++)
        t[ty + 8*i][tx] = Wsrc[(size_t)(k0 + ty + 8*i) * ldw + (n0 - noff) + tx];
    __syncthreads();
    #pragma unroll
    for (int i = 0; i < 4; i++) {
        const int n = n0 + ty + 8*i;
        unsigned short hi, lo;
        splitf(t[tx][ty + 8*i], hi, lo);
        g_Bh[(size_t)n * KDIM + k0 + tx] = __ushort_as_bfloat16(hi);
        g_Bl[(size_t)n * KDIM + k0 + tx] = __ushort_as_bfloat16(lo);
    }
    if (blockIdx.x == 0 && ty == 0) {
        const int n = n0 + tx;
        const float* bsrc = (n < 512) ? b1 : (n < 768 ? bd : bu);
        const int off = (n < 512) ? 0 : (n < 768 ? 512 : 768);
        g_ball[n] = bsrc[n - off];
    }
}

// ---------------------------------------------------------------------------
// GEMM: BM=128, BN=256, BK=32; 512 thr (4m x 4n warps, warp tile 32x64);
// 3-stage cp.async, ONE __syncthreads per stage; rows padded to 80B.
// ---------------------------------------------------------------------------
#define ROWB     80
#define OFF_AH   0
#define OFF_AL   10240            // 128*80
#define OFF_BH   20480
#define OFF_BL   40960            // 20480 + 256*80
#define ST_BYTES 61440            // 60KB per stage
#define NSTAGE   3
#define SMEM_TOTAL (NSTAGE * ST_BYTES)   // 180KB
#define KSTAGES  (KDIM / 32)      // 136

__global__ __launch_bounds__(512, 1)
void gemm1_mma()
{
    extern __shared__ char smem[];
    const uint32_t sb = smem_u32(smem);
    const int tid  = threadIdx.x;
    const int wid  = tid >> 5;
    const int lane = tid & 31;
    const int bx = blockIdx.x;   // n-tile 0..3
    const int by = blockIdx.y;   // m-tile 0..63

    const __nv_bfloat16* baseA[2] = {
        g_Ah + (size_t)(by * 128) * KDIM,
        g_Al + (size_t)(by * 128) * KDIM
    };
    const __nv_bfloat16* baseB[2] = {
        g_Bh + (size_t)(bx * 256) * KDIM,
        g_Bl + (size_t)(bx * 256) * KDIM
    };

    // 3072 16B-chunks per stage, 6 per thread
    auto load_stage = [&](int s) {
        const uint32_t st = sb + (uint32_t)(s % NSTAGE) * ST_BYTES;
        const int koff = s * 32;
        #pragma unroll
        for (int t = 0; t < 6; t++) {
            const int c = t * 512 + tid;
            const __nv_bfloat16* src;
            uint32_t dst;
            if (c < 1024) {                   // A planes
                const int p = c >> 9, idx = c & 511;
                const int row = idx >> 2, g = idx & 3;
                src = baseA[p] + (size_t)row * KDIM + koff + g * 8;
                dst = st + (p ? OFF_AL : OFF_AH) + row * ROWB + g * 16;
            } else {                          // B planes
                const int c2 = c - 1024;
                const int p = c2 >> 10, idx = c2 & 1023;
                const int row = idx >> 2, g = idx & 3;
                src = baseB[p] + (size_t)row * KDIM + koff + g * 8;
                dst = st + (p ? OFF_BL : OFF_BH) + row * ROWB + g * 16;
            }
            CP_ASYNC16(dst, src);
        }
        CP_COMMIT();
    };

    const int wm = wid & 3;        // m-warp 0..3
    const int wn = wid >> 2;       // n-warp 0..3
    const int rsel = lane & 15;
    const int bsel = lane >> 4;

    float acc[2][8][4];
    #pragma unroll
    for (int mf = 0; mf < 2; mf++)
        #pragma unroll
        for (int nf = 0; nf < 8; nf++)
            #pragma unroll
            for (int q = 0; q < 4; q++) acc[mf][nf][q] = 0.f;

    load_stage(0);
    load_stage(1);

    #pragma unroll 1
    for (int s = 0; s < KSTAGES; s++) {
        if (s + 1 < KSTAGES) { CP_WAIT1(); } else { CP_WAIT0(); }
        __syncthreads();
        if (s + 2 < KSTAGES) load_stage(s + 2);   // buffer consumed at s-1; safe

        const uint32_t st = sb + (uint32_t)(s % NSTAGE) * ST_BYTES;
        const uint32_t ra = (uint32_t)(wm * 32 + rsel) * ROWB;
        const uint32_t rb = (uint32_t)(wn * 64 + rsel) * ROWB;

        // hoist ALL A fragments for both kk steps (long dep distance)
        uint32_t Ah[2][2][4], Al[2][2][4];
        #pragma unroll
        for (int kk = 0; kk < 2; kk++) {
            const uint32_t kaddr = (uint32_t)(((kk << 1) + bsel) << 4);
            #pragma unroll
            for (int mf = 0; mf < 2; mf++) {
                const uint32_t r = ra + (uint32_t)(mf * 16) * ROWB + kaddr;
                LDSM4(Ah[kk][mf], st + OFF_AH + r);
                LDSM4(Al[kk][mf], st + OFF_AL + r);
            }
        }
        #pragma unroll
        for (int kk = 0; kk < 2; kk++) {
            const uint32_t kaddr = (uint32_t)(((kk << 1) + bsel) << 4);
            #pragma unroll
            for (int j = 0; j < 4; j++) {
                uint32_t Bh[4], Bl[4];
                const uint32_t r = rb + (uint32_t)(j * 16) * ROWB + kaddr;
                LDSM4(Bh, st + OFF_BH + r);
                LDSM4(Bl, st + OFF_BL + r);
                #pragma unroll
                for (int mf = 0; mf < 2; mf++)
                    #pragma unroll
                    for (int pp = 0; pp < 2; pp++) {
                        const int nf = j * 2 + pp;
                        MMA16816(acc[mf][nf], Ah[kk][mf], Bh[pp], Bh[2 + pp]);
                        MMA16816(acc[mf][nf], Ah[kk][mf], Bl[pp], Bl[2 + pp]);
                        MMA16816(acc[mf][nf], Al[kk][mf], Bh[pp], Bh[2 + pp]);
                    }
            }
        }
    }

    // epilogue: add bias, store fp32
    const int g  = lane >> 2;
    const int t2 = (lane & 3) * 2;
    const int ncol0 = bx * 256 + wn * 64;
    #pragma unroll
    for (int mf = 0; mf < 2; mf++) {
        const int m = by * 128 + wm * 32 + mf * 16 + g;
        float* y0 = g_Y + (size_t)m * NTOT + ncol0;
        float* y1 = y0 + (size_t)8 * NTOT;
        #pragma unroll
        for (int nf = 0; nf < 8; nf++) {
            const int nn = nf * 8 + t2;
            const float bz0 = g_ball[ncol0 + nn];
            const float bz1 = g_ball[ncol0 + nn + 1];
            *reinterpret_cast<float2*>(y0 + nn) =
                make_float2(acc[mf][nf][0] + bz0, acc[mf][nf][1] + bz1);
            *reinterpret_cast<float2*>(y1 + nn) =
                make_float2(acc[mf][nf][2] + bz0, acc[mf][nf][3] + bz1);
        }
    }
}

// ---------------------------------------------------------------------------
// Kernel 2: LN + exact GELU + GEMM2 + gates + L2 renorm
// ---------------------------------------------------------------------------
__global__ __launch_bounds__(256, 3)
void fuse2_kernel(const float* __restrict__ h,
                  const float* __restrict__ gam, const float* __restrict__ bet,
                  const float* __restrict__ W2, const float* __restrict__ b2,
                  float* __restrict__ out)
{
    constexpr int ROWS = 16;
    __shared__ float s_t[ROWS * 512];
    __shared__ float s_red[2 * ROWS * 8];
    __shared__ float s_scale[ROWS];

    const int tid  = threadIdx.x;
    const int w    = tid >> 5;
    const int lane = tid & 31;
    const int row0 = blockIdx.x * ROWS;

    #pragma unroll
    for (int rr = 0; rr < 2; ++rr) {
        const int r = w + rr * 8;
        const float* yrow = g_Y + (size_t)(row0 + r) * NTOT;
        float vals[16];
        float s = 0.f, s2 = 0.f;
        #pragma unroll
        for (int q = 0; q < 4; q++) {
            float4 v = *reinterpret_cast<const float4*>(yrow + (lane + q * 32) * 4);
            vals[q*4+0] = v.x; vals[q*4+1] = v.y; vals[q*4+2] = v.z; vals[q*4+3] = v.w;
            s  += v.x + v.y + v.z + v.w;
            s2 += v.x*v.x + v.y*v.y + v.z*v.z + v.w*v.w;
        }
        #pragma unroll
        for (int o = 16; o; o >>= 1) {
            s  += __shfl_xor_sync(0xffffffffu, s,  o);
            s2 += __shfl_xor_sync(0xffffffffu, s2, o);
        }
        const float mu   = s * (1.f / 512.f);
        const float var  = s2 * (1.f / 512.f) - mu * mu;
        const float rstd = rsqrtf(var + 1e-5f);
        #pragma unroll
        for (int q = 0; q < 4; q++) {
            const int c = (lane + q * 32) * 4;
            float4 gv = *reinterpret_cast<const float4*>(gam + c);
            float4 bv = *reinterpret_cast<const float4*>(bet + c);
            float g4[4]  = {gv.x, gv.y, gv.z, gv.w};
            float be4[4] = {bv.x, bv.y, bv.z, bv.w};
            #pragma unroll
            for (int e = 0; e < 4; e++) {
                float t = (vals[q*4+e] - mu) * rstd * g4[e] + be4[e];
                s_t[r * 512 + c + e] = 0.5f * t * (1.f + erff(t * 0.7071067811865475f));
            }
        }
    }
    __syncthreads();

    const int j = tid;
    float acc[ROWS];
    #pragma unroll
    for (int r = 0; r < ROWS; r++) acc[r] = 0.f;

    #pragma unroll 2
    for (int k0 = 0; k0 < 512; k0 += 4) {
        float w0 = W2[(size_t)(k0 + 0) * 256 + j];
        float w1 = W2[(size_t)(k0 + 1) * 256 + j];
        float w2 = W2[(size_t)(k0 + 2) * 256 + j];
        float w3 = W2[(size_t)(k0 + 3) * 256 + j];
        #pragma unroll
        for (int r = 0; r < ROWS; r++) {
            float4 tv = *reinterpret_cast<const float4*>(&s_t[r * 512 + k0]);
            acc[r] = fmaf(tv.x, w0, acc[r]);
            acc[r] = fmaf(tv.y, w1, acc[r]);
            acc[r] = fmaf(tv.z, w2, acc[r]);
            acc[r] = fmaf(tv.w, w3, acc[r]);
        }
    }

    const float b2j = b2[j];
    #pragma unroll
    for (int r = 0; r < ROWS; r++) {
        const int rg = row0 + r;
        const float* yrow = g_Y + (size_t)rg * NTOT;
        const float hc  = tanhf(acc[r] + b2j);
        const float dec = 1.f / (1.f + __expf(-yrow[512 + j]));
        const float ts  = 0.1f + 9.9f * dec + 1e-6f;
        const float u   = 1.f / (1.f + __expf(-yrow[768 + j]));
        const float hv  = h[(size_t)rg * MEMD + j];
        const float nh  = (1.f - u) * (hv / ts) + u * hc;
        acc[r] = nh;
        float ph = hv * hv, pn = nh * nh;
        #pragma unroll
        for (int o = 16; o; o >>= 1) {
            ph += __shfl_xor_sync(0xffffffffu, ph, o);
            pn += __shfl_xor_sync(0xffffffffu, pn, o);
        }
        if (lane == 0) { s_red[r*8 + w] = ph; s_red[128 + r*8 + w] = pn; }
    }
    __syncthreads();

    if (tid < ROWS) {
        float h2 = 0.f, n2 = 0.f;
        #pragma unroll
        for (int q = 0; q < 8; q++) { h2 += s_red[tid*8+q]; n2 += s_red[128 + tid*8+q]; }
        s_scale[tid] = fmaxf(sqrtf(h2), 1e-6f) / fmaxf(sqrtf(n2), 1e-12f);
    }
    __syncthreads();

    #pragma unroll
    for (int r = 0; r < ROWS; r++)
        out[(size_t)(row0 + r) * MEMD + j] = acc[r] * s_scale[r];
}

// ---------------------------------------------------------------------------
extern "C" void kernel_launch(void* const* d_in, const int* in_sizes, int n_in,
                              void* d_out, int out_size)
{
    (void)in_sizes; (void)n_in; (void)out_size;
    const float* x   = (const float*)d_in[0];
    const float* h   = (const float*)d_in[1];
    const float* W1  = (const float*)d_in[2];
    const float* b1  = (const float*)d_in[3];
    const float* gam = (const float*)d_in[4];
    const float* bet = (const float*)d_in[5];
    const float* W2  = (const float*)d_in[6];
    const float* b2  = (const float*)d_in[7];
    const float* Wd  = (const float*)d_in[8];
    const float* bd  = (const float*)d_in[9];
    const float* Wu  = (const float*)d_in[10];
    const float* bu  = (const float*)d_in[11];
    float* out = (float*)d_out;

    cudaFuncSetAttribute(gemm1_mma, cudaFuncAttributeMaxDynamicSharedMemorySize, SMEM_TOTAL);

    prep_a<<<(BATCH * (KDIM / 8)) / 256, 256>>>(x, h);
    prep_w<<<dim3(KDIM / 32, NTOT / 32), dim3(32, 8)>>>(W1, Wd, Wu, b1, bd, bu);

    dim3 ggrid(NTOT / 256, BATCH / 128);   // 4 x 64
    gemm1_mma<<<ggrid, 512, SMEM_TOTAL>>>();

    fuse2_kernel<<<BATCH / 16, 256>>>(h, gam, bet, W2, b2, out);
}

// round 10
// speedup vs baseline: 1.4036x; 1.4036x over previous
#include <cuda_runtime.h>
#include <cuda_fp16.h>
#include <math.h>
#include <cstdint>

#define BATCH  8192
#define IN_DIM 4096
#define MEMD   256
#define KDIM   4352
#define NTOT   1024

// gmem scratch (fp16 planes)
__device__ float  g_Y [(size_t)BATCH * NTOT];
__device__ __half g_Ah[(size_t)BATCH * KDIM];
__device__ __half g_Al[(size_t)BATCH * KDIM];
__device__ __half g_Bh[(size_t)NTOT  * KDIM];
__device__ float  g_ball[NTOT];

// ------------------------------- helpers ----------------------------------
__device__ __forceinline__ uint32_t smem_u32(const void* p){
    uint32_t a;
    asm("{ .reg .u64 t; cvta.to.shared.u64 t, %1; cvt.u32.u64 %0, t; }" : "=r"(a) : "l"(p));
    return a;
}
__device__ __forceinline__ void splith(float v, unsigned short& hi, unsigned short& lo){
    __half h = __float2half_rn(v);
    __half l = __float2half_rn(v - __half2float(h));
    hi = __half_as_ushort(h);
    lo = __half_as_ushort(l);
}

#define CP_ASYNC16(dst, src) \
    asm volatile("cp.async.cg.shared.global [%0], [%1], 16;" :: "r"(dst), "l"(src))
#define CP_COMMIT() asm volatile("cp.async.commit_group;" ::: "memory")
#define CP_WAIT1()  asm volatile("cp.async.wait_group 1;" ::: "memory")
#define CP_WAIT0()  asm volatile("cp.async.wait_group 0;" ::: "memory")

#define LDSM4(r, addr) \
    asm volatile("ldmatrix.sync.aligned.m8n8.x4.shared.b16 {%0,%1,%2,%3}, [%4];" \
        : "=r"((r)[0]), "=r"((r)[1]), "=r"((r)[2]), "=r"((r)[3]) : "r"(addr))

#define MMAF16(d, a, b0, b1) \
    asm volatile("mma.sync.aligned.m16n8k16.row.col.f32.f16.f16.f32 " \
        "{%0,%1,%2,%3}, {%4,%5,%6,%7}, {%8,%9}, {%0,%1,%2,%3};" \
        : "+f"((d)[0]), "+f"((d)[1]), "+f"((d)[2]), "+f"((d)[3]) \
        : "r"((a)[0]), "r"((a)[1]), "r"((a)[2]), "r"((a)[3]), "r"(b0), "r"(b1))

// ---------------------------------------------------------------------------
// Prep A: split [h|x] -> fp16 hi/lo planes, row-major [m][k]
// ---------------------------------------------------------------------------
__global__ __launch_bounds__(256)
void prep_a(const float* __restrict__ x, const float* __restrict__ h)
{
    const int id = blockIdx.x * 256 + threadIdx.x;
    const int m  = id / 544;
    const int k  = (id % 544) * 8;
    const float* src = (k < MEMD) ? h + (size_t)m * MEMD + k
                                  : x + (size_t)m * IN_DIM + (k - MEMD);
    float4 v0 = *reinterpret_cast<const float4*>(src);
    float4 v1 = *reinterpret_cast<const float4*>(src + 4);
    float vv[8] = {v0.x, v0.y, v0.z, v0.w, v1.x, v1.y, v1.z, v1.w};
    unsigned short hs[8], ls[8];
    #pragma unroll
    for (int i = 0; i < 8; i++) splith(vv[i], hs[i], ls[i]);
    uint4 H, L;
    H.x = hs[0] | ((uint32_t)hs[1] << 16);  H.y = hs[2] | ((uint32_t)hs[3] << 16);
    H.z = hs[4] | ((uint32_t)hs[5] << 16);  H.w = hs[6] | ((uint32_t)hs[7] << 16);
    L.x = ls[0] | ((uint32_t)ls[1] << 16);  L.y = ls[2] | ((uint32_t)ls[3] << 16);
    L.z = ls[4] | ((uint32_t)ls[5] << 16);  L.w = ls[6] | ((uint32_t)ls[7] << 16);
    *reinterpret_cast<uint4*>(g_Ah + (size_t)m * KDIM + k) = H;
    *reinterpret_cast<uint4*>(g_Al + (size_t)m * KDIM + k) = L;
}

// ---------------------------------------------------------------------------
// Prep W: transpose+concat [W1|Wd|Wu] -> single fp16 plane [n][k]
// ---------------------------------------------------------------------------
__global__ void prep_w(const float* __restrict__ W1, const float* __restrict__ Wd,
                       const float* __restrict__ Wu,
                       const float* __restrict__ b1, const float* __restrict__ bd,
                       const float* __restrict__ bu)
{
    __shared__ float t[32][33];
    const int k0 = blockIdx.x * 32, n0 = blockIdx.y * 32;
    const int tx = threadIdx.x, ty = threadIdx.y;
    const float* Wsrc; int ldw, noff;
    if (n0 < 512)      { Wsrc = W1; ldw = 512; noff = 0; }
    else if (n0 < 768) { Wsrc = Wd; ldw = 256; noff = 512; }
    else               { Wsrc = Wu; ldw = 256; noff = 768; }
    #pragma unroll
    for (int i = 0; i < 4; i++)
        t[ty + 8*i][tx] = Wsrc[(size_t)(k0 + ty + 8*i) * ldw + (n0 - noff) + tx];
    __syncthreads();
    #pragma unroll
    for (int i = 0; i < 4; i++) {
        const int n = n0 + ty + 8*i;
        g_Bh[(size_t)n * KDIM + k0 + tx] = __float2half_rn(t[tx][ty + 8*i]);
    }
    if (blockIdx.x == 0 && ty == 0) {
        const int n = n0 + tx;
        const float* bsrc = (n < 512) ? b1 : (n < 768 ? bd : bu);
        const int off = (n < 512) ? 0 : (n < 768 ? 512 : 768);
        g_ball[n] = bsrc[n - off];
    }
}

// ---------------------------------------------------------------------------
// GEMM: BM=128, BN=256, BK=64; 512 thr (4m x 4n warps, warp tile 32x64);
// 3-stage cp.async, one __syncthreads per stage; rows padded to 144B.
// 2-pass fp16: acc += Ah*Bh + Al*Bh
// ---------------------------------------------------------------------------
#define ROWB     144
#define OFF_AH   0
#define OFF_AL   18432            // 128*144
#define OFF_BH   36864
#define ST_BYTES 73728            // + 256*144 = 72KB per stage
#define NSTAGE   3
#define SMEM_TOTAL (NSTAGE * ST_BYTES)   // 216KB
#define KSTAGES  (KDIM / 64)      // 68

__global__ __launch_bounds__(512, 1)
void gemm1_mma()
{
    extern __shared__ char smem[];
    const uint32_t sb = smem_u32(smem);
    const int tid  = threadIdx.x;
    const int wid  = tid >> 5;
    const int lane = tid & 31;
    const int bx = blockIdx.x;   // n-tile 0..3
    const int by = blockIdx.y;   // m-tile 0..63

    const __half* baseA[2] = {
        g_Ah + (size_t)(by * 128) * KDIM,
        g_Al + (size_t)(by * 128) * KDIM
    };
    const __half* baseB = g_Bh + (size_t)(bx * 256) * KDIM;

    // 4096 16B-chunks per stage (A: 2048, B: 2048), 8 per thread
    auto load_stage = [&](int s) {
        const uint32_t st = sb + (uint32_t)(s % NSTAGE) * ST_BYTES;
        const int koff = s * 64;
        #pragma unroll
        for (int t = 0; t < 8; t++) {
            const int c = t * 512 + tid;
            const __half* src;
            uint32_t dst;
            if (c < 2048) {                   // A planes (hi, lo)
                const int p = c >> 10, idx = c & 1023;
                const int row = idx >> 3, g = idx & 7;
                src = baseA[p] + (size_t)row * KDIM + koff + g * 8;
                dst = st + (p ? OFF_AL : OFF_AH) + row * ROWB + g * 16;
            } else {                          // B plane
                const int c2 = c - 2048;
                const int row = c2 >> 3, g = c2 & 7;
                src = baseB + (size_t)row * KDIM + koff + g * 8;
                dst = st + OFF_BH + row * ROWB + g * 16;
            }
            CP_ASYNC16(dst, src);
        }
        CP_COMMIT();
    };

    const int wm = wid & 3;        // m-warp 0..3
    const int wn = wid >> 2;       // n-warp 0..3
    const int rsel = lane & 15;
    const int bsel = lane >> 4;

    float acc[2][8][4];
    #pragma unroll
    for (int mf = 0; mf < 2; mf++)
        #pragma unroll
        for (int nf = 0; nf < 8; nf++)
            #pragma unroll
            for (int q = 0; q < 4; q++) acc[mf][nf][q] = 0.f;

    load_stage(0);
    load_stage(1);

    #pragma unroll 1
    for (int s = 0; s < KSTAGES; s++) {
        if (s + 1 < KSTAGES) { CP_WAIT1(); } else { CP_WAIT0(); }
        __syncthreads();
        if (s + 2 < KSTAGES) load_stage(s + 2);   // targets buffer consumed at s-1

        const uint32_t st = sb + (uint32_t)(s % NSTAGE) * ST_BYTES;
        const uint32_t ra = (uint32_t)(wm * 32 + rsel) * ROWB;
        const uint32_t rb = (uint32_t)(wn * 64 + rsel) * ROWB;

        #pragma unroll
        for (int kk = 0; kk < 4; kk++) {
            const uint32_t kaddr = (uint32_t)(((kk << 1) + bsel) << 4);
            uint32_t Ah[2][4], Al[2][4];
            #pragma unroll
            for (int mf = 0; mf < 2; mf++) {
                const uint32_t r = ra + (uint32_t)(mf * 16) * ROWB + kaddr;
                LDSM4(Ah[mf], st + OFF_AH + r);
                LDSM4(Al[mf], st + OFF_AL + r);
            }
            #pragma unroll
            for (int j = 0; j < 4; j++) {
                uint32_t Bh[4];
                const uint32_t r = rb + (uint32_t)(j * 16) * ROWB + kaddr;
                LDSM4(Bh, st + OFF_BH + r);
                #pragma unroll
                for (int mf = 0; mf < 2; mf++)
                    #pragma unroll
                    for (int pp = 0; pp < 2; pp++) {
                        const int nf = j * 2 + pp;
                        MMAF16(acc[mf][nf], Ah[mf], Bh[pp], Bh[2 + pp]);
                        MMAF16(acc[mf][nf], Al[mf], Bh[pp], Bh[2 + pp]);
                    }
            }
        }
    }

    // epilogue: add bias, store fp32
    const int g  = lane >> 2;
    const int t2 = (lane & 3) * 2;
    const int ncol0 = bx * 256 + wn * 64;
    #pragma unroll
    for (int mf = 0; mf < 2; mf++) {
        const int m = by * 128 + wm * 32 + mf * 16 + g;
        float* y0 = g_Y + (size_t)m * NTOT + ncol0;
        float* y1 = y0 + (size_t)8 * NTOT;
        #pragma unroll
        for (int nf = 0; nf < 8; nf++) {
            const int nn = nf * 8 + t2;
            const float bz0 = g_ball[ncol0 + nn];
            const float bz1 = g_ball[ncol0 + nn + 1];
            *reinterpret_cast<float2*>(y0 + nn) =
                make_float2(acc[mf][nf][0] + bz0, acc[mf][nf][1] + bz1);
            *reinterpret_cast<float2*>(y1 + nn) =
                make_float2(acc[mf][nf][2] + bz0, acc[mf][nf][3] + bz1);
        }
    }
}

// ---------------------------------------------------------------------------
// Kernel 2: LN + exact GELU + GEMM2 + gates + L2 renorm (round-7 config)
// ---------------------------------------------------------------------------
__global__ __launch_bounds__(256)
void fuse2_kernel(const float* __restrict__ h,
                  const float* __restrict__ gam, const float* __restrict__ bet,
                  const float* __restrict__ W2, const float* __restrict__ b2,
                  float* __restrict__ out)
{
    constexpr int ROWS = 16;
    __shared__ float s_t[ROWS * 512];
    __shared__ float s_red[2 * ROWS * 8];
    __shared__ float s_scale[ROWS];

    const int tid  = threadIdx.x;
    const int w    = tid >> 5;
    const int lane = tid & 31;
    const int row0 = blockIdx.x * ROWS;

    #pragma unroll
    for (int rr = 0; rr < 2; ++rr) {
        const int r = w + rr * 8;
        const float* yrow = g_Y + (size_t)(row0 + r) * NTOT;
        float vals[16];
        float s = 0.f, s2 = 0.f;
        #pragma unroll
        for (int q = 0; q < 4; q++) {
            float4 v = *reinterpret_cast<const float4*>(yrow + (lane + q * 32) * 4);
            vals[q*4+0] = v.x; vals[q*4+1] = v.y; vals[q*4+2] = v.z; vals[q*4+3] = v.w;
            s  += v.x + v.y + v.z + v.w;
            s2 += v.x*v.x + v.y*v.y + v.z*v.z + v.w*v.w;
        }
        #pragma unroll
        for (int o = 16; o; o >>= 1) {
            s  += __shfl_xor_sync(0xffffffffu, s,  o);
            s2 += __shfl_xor_sync(0xffffffffu, s2, o);
        }
        const float mu   = s * (1.f / 512.f);
        const float var  = s2 * (1.f / 512.f) - mu * mu;
        const float rstd = rsqrtf(var + 1e-5f);
        #pragma unroll
        for (int q = 0; q < 4; q++) {
            const int c = (lane + q * 32) * 4;
            float4 gv = *reinterpret_cast<const float4*>(gam + c);
            float4 bv = *reinterpret_cast<const float4*>(bet + c);
            float g4[4]  = {gv.x, gv.y, gv.z, gv.w};
            float be4[4] = {bv.x, bv.y, bv.z, bv.w};
            #pragma unroll
            for (int e = 0; e < 4; e++) {
                float t = (vals[q*4+e] - mu) * rstd * g4[e] + be4[e];
                s_t[r * 512 + c + e] = 0.5f * t * (1.f + erff(t * 0.7071067811865475f));
            }
        }
    }
    __syncthreads();

    const int j = tid;
    float acc[ROWS];
    #pragma unroll
    for (int r = 0; r < ROWS; r++) acc[r] = 0.f;

    #pragma unroll 2
    for (int k0 = 0; k0 < 512; k0 += 4) {
        float w0 = W2[(size_t)(k0 + 0) * 256 + j];
        float w1 = W2[(size_t)(k0 + 1) * 256 + j];
        float w2 = W2[(size_t)(k0 + 2) * 256 + j];
        float w3 = W2[(size_t)(k0 + 3) * 256 + j];
        #pragma unroll
        for (int r = 0; r < ROWS; r++) {
            float4 tv = *reinterpret_cast<const float4*>(&s_t[r * 512 + k0]);
            acc[r] = fmaf(tv.x, w0, acc[r]);
            acc[r] = fmaf(tv.y, w1, acc[r]);
            acc[r] = fmaf(tv.z, w2, acc[r]);
            acc[r] = fmaf(tv.w, w3, acc[r]);
        }
    }

    const float b2j = b2[j];
    #pragma unroll
    for (int r = 0; r < ROWS; r++) {
        const int rg = row0 + r;
        const float* yrow = g_Y + (size_t)rg * NTOT;
        const float hc  = tanhf(acc[r] + b2j);
        const float dec = 1.f / (1.f + __expf(-yrow[512 + j]));
        const float ts  = 0.1f + 9.9f * dec + 1e-6f;
        const float u   = 1.f / (1.f + __expf(-yrow[768 + j]));
        const float hv  = h[(size_t)rg * MEMD + j];
        const float nh  = (1.f - u) * (hv / ts) + u * hc;
        acc[r] = nh;
        float ph = hv * hv, pn = nh * nh;
        #pragma unroll
        for (int o = 16; o; o >>= 1) {
            ph += __shfl_xor_sync(0xffffffffu, ph, o);
            pn += __shfl_xor_sync(0xffffffffu, pn, o);
        }
        if (lane == 0) { s_red[r*8 + w] = ph; s_red[128 + r*8 + w] = pn; }
    }
    __syncthreads();

    if (tid < ROWS) {
        float h2 = 0.f, n2 = 0.f;
        #pragma unroll
        for (int q = 0; q < 8; q++) { h2 += s_red[tid*8+q]; n2 += s_red[128 + tid*8+q]; }
        s_scale[tid] = fmaxf(sqrtf(h2), 1e-6f) / fmaxf(sqrtf(n2), 1e-12f);
    }
    __syncthreads();

    #pragma unroll
    for (int r = 0; r < ROWS; r++)
        out[(size_t)(row0 + r) * MEMD + j] = acc[r] * s_scale[r];
}

// ---------------------------------------------------------------------------
extern "C" void kernel_launch(void* const* d_in, const int* in_sizes, int n_in,
                              void* d_out, int out_size)
{
    (void)in_sizes; (void)n_in; (void)out_size;
    const float* x   = (const float*)d_in[0];
    const float* h   = (const float*)d_in[1];
    const float* W1  = (const float*)d_in[2];
    const float* b1  = (const float*)d_in[3];
    const float* gam = (const float*)d_in[4];
    const float* bet = (const float*)d_in[5];
    const float* W2  = (const float*)d_in[6];
    const float* b2  = (const float*)d_in[7];
    const float* Wd  = (const float*)d_in[8];
    const float* bd  = (const float*)d_in[9];
    const float* Wu  = (const float*)d_in[10];
    const float* bu  = (const float*)d_in[11];
    float* out = (float*)d_out;

    cudaFuncSetAttribute(gemm1_mma, cudaFuncAttributeMaxDynamicSharedMemorySize, SMEM_TOTAL);

    prep_a<<<(BATCH * (KDIM / 8)) / 256, 256>>>(x, h);
    prep_w<<<dim3(KDIM / 32, NTOT / 32), dim3(32, 8)>>>(W1, Wd, Wu, b1, bd, bu);

    dim3 ggrid(NTOT / 256, BATCH / 128);   // 4 x 64
    gemm1_mma<<<ggrid, 512, SMEM_TOTAL>>>();

    fuse2_kernel<<<BATCH / 16, 256>>>(h, gam, bet, W2, b2, out);
}

// round 11
// speedup vs baseline: 2.0947x; 1.4923x over previous
#include <cuda_runtime.h>
#include <cuda_fp16.h>
#include <math.h>
#include <cstdint>

#define BATCH  8192
#define IN_DIM 4096
#define MEMD   256
#define KDIM   4352
#define NTOT   1024

// gmem scratch (fp16 planes)
__device__ float  g_Y [(size_t)BATCH * NTOT];
__device__ __half g_Ah[(size_t)BATCH * KDIM];
__device__ __half g_Bh[(size_t)NTOT  * KDIM];
__device__ float  g_ball[NTOT];

// ------------------------------- helpers ----------------------------------
__device__ __forceinline__ uint32_t smem_u32(const void* p){
    uint32_t a;
    asm("{ .reg .u64 t; cvta.to.shared.u64 t, %1; cvt.u32.u64 %0, t; }" : "=r"(a) : "l"(p));
    return a;
}

#define CP_ASYNC16(dst, src) \
    asm volatile("cp.async.cg.shared.global [%0], [%1], 16;" :: "r"(dst), "l"(src))
#define CP_COMMIT() asm volatile("cp.async.commit_group;" ::: "memory")
#define CP_WAIT1()  asm volatile("cp.async.wait_group 1;" ::: "memory")
#define CP_WAIT0()  asm volatile("cp.async.wait_group 0;" ::: "memory")

#define LDSM4(r, addr) \
    asm volatile("ldmatrix.sync.aligned.m8n8.x4.shared.b16 {%0,%1,%2,%3}, [%4];" \
        : "=r"((r)[0]), "=r"((r)[1]), "=r"((r)[2]), "=r"((r)[3]) : "r"(addr))

#define MMAF16(d, a, b0, b1) \
    asm volatile("mma.sync.aligned.m16n8k16.row.col.f32.f16.f16.f32 " \
        "{%0,%1,%2,%3}, {%4,%5,%6,%7}, {%8,%9}, {%0,%1,%2,%3};" \
        : "+f"((d)[0]), "+f"((d)[1]), "+f"((d)[2]), "+f"((d)[3]) \
        : "r"((a)[0]), "r"((a)[1]), "r"((a)[2]), "r"((a)[3]), "r"(b0), "r"(b1))

// ---------------------------------------------------------------------------
// Prep A: convert [h|x] -> fp16 plane, row-major [m][k]
// ---------------------------------------------------------------------------
__global__ __launch_bounds__(256)
void prep_a(const float* __restrict__ x, const float* __restrict__ h)
{
    const int id = blockIdx.x * 256 + threadIdx.x;
    const int m  = id / 544;
    const int k  = (id % 544) * 8;
    const float* src = (k < MEMD) ? h + (size_t)m * MEMD + k
                                  : x + (size_t)m * IN_DIM + (k - MEMD);
    float4 v0 = *reinterpret_cast<const float4*>(src);
    float4 v1 = *reinterpret_cast<const float4*>(src + 4);
    float vv[8] = {v0.x, v0.y, v0.z, v0.w, v1.x, v1.y, v1.z, v1.w};
    unsigned short hs[8];
    #pragma unroll
    for (int i = 0; i < 8; i++) hs[i] = __half_as_ushort(__float2half_rn(vv[i]));
    uint4 H;
    H.x = hs[0] | ((uint32_t)hs[1] << 16);  H.y = hs[2] | ((uint32_t)hs[3] << 16);
    H.z = hs[4] | ((uint32_t)hs[5] << 16);  H.w = hs[6] | ((uint32_t)hs[7] << 16);
    *reinterpret_cast<uint4*>(g_Ah + (size_t)m * KDIM + k) = H;
}

// ---------------------------------------------------------------------------
// Prep W: transpose+concat [W1|Wd|Wu] -> single fp16 plane [n][k]
// ---------------------------------------------------------------------------
__global__ void prep_w(const float* __restrict__ W1, const float* __restrict__ Wd,
                       const float* __restrict__ Wu,
                       const float* __restrict__ b1, const float* __restrict__ bd,
                       const float* __restrict__ bu)
{
    __shared__ float t[32][33];
    const int k0 = blockIdx.x * 32, n0 = blockIdx.y * 32;
    const int tx = threadIdx.x, ty = threadIdx.y;
    const float* Wsrc; int ldw, noff;
    if (n0 < 512)      { Wsrc = W1; ldw = 512; noff = 0; }
    else if (n0 < 768) { Wsrc = Wd; ldw = 256; noff = 512; }
    else               { Wsrc = Wu; ldw = 256; noff = 768; }
    #pragma unroll
    for (int i = 0; i < 4; i++)
        t[ty + 8*i][tx] = Wsrc[(size_t)(k0 + ty + 8*i) * ldw + (n0 - noff) + tx];
    __syncthreads();
    #pragma unroll
    for (int i = 0; i < 4; i++) {
        const int n = n0 + ty + 8*i;
        g_Bh[(size_t)n * KDIM + k0 + tx] = __float2half_rn(t[tx][ty + 8*i]);
    }
    if (blockIdx.x == 0 && ty == 0) {
        const int n = n0 + tx;
        const float* bsrc = (n < 512) ? b1 : (n < 768 ? bd : bu);
        const int off = (n < 512) ? 0 : (n < 768 ? 512 : 768);
        g_ball[n] = bsrc[n - off];
    }
}

// ---------------------------------------------------------------------------
// GEMM: BM=128, BN=256, BK=64; 512 thr (4m x 4n warps, warp tile 32x64);
// 3-stage cp.async; rows padded to 144B. Single fp16 pass: acc += Ah*Bh
// ---------------------------------------------------------------------------
#define ROWB     144
#define OFF_AH   0
#define OFF_BH   18432            // 128*144
#define ST_BYTES 55296            // + 256*144 = 54KB per stage
#define NSTAGE   3
#define SMEM_TOTAL (NSTAGE * ST_BYTES)   // 162KB
#define KSTAGES  (KDIM / 64)      // 68

__global__ __launch_bounds__(512, 1)
void gemm1_mma()
{
    extern __shared__ char smem[];
    const uint32_t sb = smem_u32(smem);
    const int tid  = threadIdx.x;
    const int wid  = tid >> 5;
    const int lane = tid & 31;
    const int bx = blockIdx.x;   // n-tile 0..3
    const int by = blockIdx.y;   // m-tile 0..63

    const __half* baseA = g_Ah + (size_t)(by * 128) * KDIM;
    const __half* baseB = g_Bh + (size_t)(bx * 256) * KDIM;

    // 3072 16B-chunks per stage (A: 1024, B: 2048), 6 per thread
    auto load_stage = [&](int s) {
        const uint32_t st = sb + (uint32_t)(s % NSTAGE) * ST_BYTES;
        const int koff = s * 64;
        #pragma unroll
        for (int t = 0; t < 6; t++) {
            const int c = t * 512 + tid;
            const __half* src;
            uint32_t dst;
            if (c < 1024) {                   // A plane
                const int row = c >> 3, g = c & 7;
                src = baseA + (size_t)row * KDIM + koff + g * 8;
                dst = st + OFF_AH + row * ROWB + g * 16;
            } else {                          // B plane
                const int c2 = c - 1024;
                const int row = c2 >> 3, g = c2 & 7;
                src = baseB + (size_t)row * KDIM + koff + g * 8;
                dst = st + OFF_BH + row * ROWB + g * 16;
            }
            CP_ASYNC16(dst, src);
        }
        CP_COMMIT();
    };

    const int wm = wid & 3;        // m-warp 0..3
    const int wn = wid >> 2;       // n-warp 0..3
    const int rsel = lane & 15;
    const int bsel = lane >> 4;

    float acc[2][8][4];
    #pragma unroll
    for (int mf = 0; mf < 2; mf++)
        #pragma unroll
        for (int nf = 0; nf < 8; nf++)
            #pragma unroll
            for (int q = 0; q < 4; q++) acc[mf][nf][q] = 0.f;

    load_stage(0);
    load_stage(1);

    #pragma unroll 1
    for (int s = 0; s < KSTAGES; s++) {
        if (s + 1 < KSTAGES) { CP_WAIT1(); } else { CP_WAIT0(); }
        __syncthreads();
        if (s + 2 < KSTAGES) load_stage(s + 2);   // targets buffer consumed at s-1

        const uint32_t st = sb + (uint32_t)(s % NSTAGE) * ST_BYTES;
        const uint32_t ra = (uint32_t)(wm * 32 + rsel) * ROWB;
        const uint32_t rb = (uint32_t)(wn * 64 + rsel) * ROWB;

        #pragma unroll
        for (int kk = 0; kk < 4; kk++) {
            const uint32_t kaddr = (uint32_t)(((kk << 1) + bsel) << 4);
            uint32_t Ah[2][4];
            #pragma unroll
            for (int mf = 0; mf < 2; mf++) {
                const uint32_t r = ra + (uint32_t)(mf * 16) * ROWB + kaddr;
                LDSM4(Ah[mf], st + OFF_AH + r);
            }
            #pragma unroll
            for (int j = 0; j < 4; j++) {
                uint32_t Bh[4];
                const uint32_t r = rb + (uint32_t)(j * 16) * ROWB + kaddr;
                LDSM4(Bh, st + OFF_BH + r);
                #pragma unroll
                for (int mf = 0; mf < 2; mf++)
                    #pragma unroll
                    for (int pp = 0; pp < 2; pp++) {
                        const int nf = j * 2 + pp;
                        MMAF16(acc[mf][nf], Ah[mf], Bh[pp], Bh[2 + pp]);
                    }
            }
        }
    }

    // epilogue: add bias, store fp32
    const int g  = lane >> 2;
    const int t2 = (lane & 3) * 2;
    const int ncol0 = bx * 256 + wn * 64;
    #pragma unroll
    for (int mf = 0; mf < 2; mf++) {
        const int m = by * 128 + wm * 32 + mf * 16 + g;
        float* y0 = g_Y + (size_t)m * NTOT + ncol0;
        float* y1 = y0 + (size_t)8 * NTOT;
        #pragma unroll
        for (int nf = 0; nf < 8; nf++) {
            const int nn = nf * 8 + t2;
            const float bz0 = g_ball[ncol0 + nn];
            const float bz1 = g_ball[ncol0 + nn + 1];
            *reinterpret_cast<float2*>(y0 + nn) =
                make_float2(acc[mf][nf][0] + bz0, acc[mf][nf][1] + bz1);
            *reinterpret_cast<float2*>(y1 + nn) =
                make_float2(acc[mf][nf][2] + bz0, acc[mf][nf][3] + bz1);
        }
    }
}

// ---------------------------------------------------------------------------
// Kernel 2: LN + exact GELU + GEMM2 + gates + L2 renorm (round-7 config)
// ---------------------------------------------------------------------------
__global__ __launch_bounds__(256)
void fuse2_kernel(const float* __restrict__ h,
                  const float* __restrict__ gam, const float* __restrict__ bet,
                  const float* __restrict__ W2, const float* __restrict__ b2,
                  float* __restrict__ out)
{
    constexpr int ROWS = 16;
    __shared__ float s_t[ROWS * 512];
    __shared__ float s_red[2 * ROWS * 8];
    __shared__ float s_scale[ROWS];

    const int tid  = threadIdx.x;
    const int w    = tid >> 5;
    const int lane = tid & 31;
    const int row0 = blockIdx.x * ROWS;

    #pragma unroll
    for (int rr = 0; rr < 2; ++rr) {
        const int r = w + rr * 8;
        const float* yrow = g_Y + (size_t)(row0 + r) * NTOT;
        float vals[16];
        float s = 0.f, s2 = 0.f;
        #pragma unroll
        for (int q = 0; q < 4; q++) {
            float4 v = *reinterpret_cast<const float4*>(yrow + (lane + q * 32) * 4);
            vals[q*4+0] = v.x; vals[q*4+1] = v.y; vals[q*4+2] = v.z; vals[q*4+3] = v.w;
            s  += v.x + v.y + v.z + v.w;
            s2 += v.x*v.x + v.y*v.y + v.z*v.z + v.w*v.w;
        }
        #pragma unroll
        for (int o = 16; o; o >>= 1) {
            s  += __shfl_xor_sync(0xffffffffu, s,  o);
            s2 += __shfl_xor_sync(0xffffffffu, s2, o);
        }
        const float mu   = s * (1.f / 512.f);
        const float var  = s2 * (1.f / 512.f) - mu * mu;
        const float rstd = rsqrtf(var + 1e-5f);
        #pragma unroll
        for (int q = 0; q < 4; q++) {
            const int c = (lane + q * 32) * 4;
            float4 gv = *reinterpret_cast<const float4*>(gam + c);
            float4 bv = *reinterpret_cast<const float4*>(bet + c);
            float g4[4]  = {gv.x, gv.y, gv.z, gv.w};
            float be4[4] = {bv.x, bv.y, bv.z, bv.w};
            #pragma unroll
            for (int e = 0; e < 4; e++) {
                float t = (vals[q*4+e] - mu) * rstd * g4[e] + be4[e];
                s_t[r * 512 + c + e] = 0.5f * t * (1.f + erff(t * 0.7071067811865475f));
            }
        }
    }
    __syncthreads();

    const int j = tid;
    float acc[ROWS];
    #pragma unroll
    for (int r = 0; r < ROWS; r++) acc[r] = 0.f;

    #pragma unroll 2
    for (int k0 = 0; k0 < 512; k0 += 4) {
        float w0 = W2[(size_t)(k0 + 0) * 256 + j];
        float w1 = W2[(size_t)(k0 + 1) * 256 + j];
        float w2 = W2[(size_t)(k0 + 2) * 256 + j];
        float w3 = W2[(size_t)(k0 + 3) * 256 + j];
        #pragma unroll
        for (int r = 0; r < ROWS; r++) {
            float4 tv = *reinterpret_cast<const float4*>(&s_t[r * 512 + k0]);
            acc[r] = fmaf(tv.x, w0, acc[r]);
            acc[r] = fmaf(tv.y, w1, acc[r]);
            acc[r] = fmaf(tv.z, w2, acc[r]);
            acc[r] = fmaf(tv.w, w3, acc[r]);
        }
    }

    const float b2j = b2[j];
    #pragma unroll
    for (int r = 0; r < ROWS; r++) {
        const int rg = row0 + r;
        const float* yrow = g_Y + (size_t)rg * NTOT;
        const float hc  = tanhf(acc[r] + b2j);
        const float dec = 1.f / (1.f + __expf(-yrow[512 + j]));
        const float ts  = 0.1f + 9.9f * dec + 1e-6f;
        const float u   = 1.f / (1.f + __expf(-yrow[768 + j]));
        const float hv  = h[(size_t)rg * MEMD + j];
        const float nh  = (1.f - u) * (hv / ts) + u * hc;
        acc[r] = nh;
        float ph = hv * hv, pn = nh * nh;
        #pragma unroll
        for (int o = 16; o; o >>= 1) {
            ph += __shfl_xor_sync(0xffffffffu, ph, o);
            pn += __shfl_xor_sync(0xffffffffu, pn, o);
        }
        if (lane == 0) { s_red[r*8 + w] = ph; s_red[128 + r*8 + w] = pn; }
    }
    __syncthreads();

    if (tid < ROWS) {
        float h2 = 0.f, n2 = 0.f;
        #pragma unroll
        for (int q = 0; q < 8; q++) { h2 += s_red[tid*8+q]; n2 += s_red[128 + tid*8+q]; }
        s_scale[tid] = fmaxf(sqrtf(h2), 1e-6f) / fmaxf(sqrtf(n2), 1e-12f);
    }
    __syncthreads();

    #pragma unroll
    for (int r = 0; r < ROWS; r++)
        out[(size_t)(row0 + r) * MEMD + j] = acc[r] * s_scale[r];
}

// ---------------------------------------------------------------------------
extern "C" void kernel_launch(void* const* d_in, const int* in_sizes, int n_in,
                              void* d_out, int out_size)
{
    (void)in_sizes; (void)n_in; (void)out_size;
    const float* x   = (const float*)d_in[0];
    const float* h   = (const float*)d_in[1];
    const float* W1  = (const float*)d_in[2];
    const float* b1  = (const float*)d_in[3];
    const float* gam = (const float*)d_in[4];
    const float* bet = (const float*)d_in[5];
    const float* W2  = (const float*)d_in[6];
    const float* b2  = (const float*)d_in[7];
    const float* Wd  = (const float*)d_in[8];
    const float* bd  = (const float*)d_in[9];
    const float* Wu  = (const float*)d_in[10];
    const float* bu  = (const float*)d_in[11];
    float* out = (float*)d_out;

    cudaFuncSetAttribute(gemm1_mma, cudaFuncAttributeMaxDynamicSharedMemorySize, SMEM_TOTAL);

    prep_a<<<(BATCH * (KDIM / 8)) / 256, 256>>>(x, h);
    prep_w<<<dim3(KDIM / 32, NTOT / 32), dim3(32, 8)>>>(W1, Wd, Wu, b1, bd, bu);

    dim3 ggrid(NTOT / 256, BATCH / 128);   // 4 x 64
    gemm1_mma<<<ggrid, 512, SMEM_TOTAL>>>();

    fuse2_kernel<<<BATCH / 16, 256>>>(h, gam, bet, W2, b2, out);
}

// round 14
// speedup vs baseline: 2.6347x; 1.2578x over previous
#include <cuda_runtime.h>
#include <cuda_fp16.h>
#include <math.h>
#include <cstdint>

#define BATCH  8192
#define IN_DIM 4096
#define MEMD   256
#define KDIM   4352
#define NTOT   1024

// gmem scratch (fp16 planes)
__device__ float  g_Y  [(size_t)BATCH * NTOT];
__device__ __half g_Ah [(size_t)BATCH * KDIM];
__device__ __half g_Bh [(size_t)NTOT  * KDIM];
__device__ __half g_W2t[(size_t)MEMD * 512];
__device__ float  g_ball[NTOT];

// ------------------------------- helpers ----------------------------------
__device__ __forceinline__ uint32_t smem_u32(const void* p){
    uint32_t a;
    asm("{ .reg .u64 t; cvta.to.shared.u64 t, %1; cvt.u32.u64 %0, t; }" : "=r"(a) : "l"(p));
    return a;
}

#define CP_ASYNC16(dst, src) \
    asm volatile("cp.async.cg.shared.global [%0], [%1], 16;" :: "r"(dst), "l"(src))
#define CP_COMMIT() asm volatile("cp.async.commit_group;" ::: "memory")
#define CP_WAIT1()  asm volatile("cp.async.wait_group 1;" ::: "memory")
#define CP_WAIT0()  asm volatile("cp.async.wait_group 0;" ::: "memory")

#define LDSM4(r, addr) \
    asm volatile("ldmatrix.sync.aligned.m8n8.x4.shared.b16 {%0,%1,%2,%3}, [%4];" \
        : "=r"((r)[0]), "=r"((r)[1]), "=r"((r)[2]), "=r"((r)[3]) : "r"(addr))

#define MMAF16(d, a, b0, b1) \
    asm volatile("mma.sync.aligned.m16n8k16.row.col.f32.f16.f16.f32 " \
        "{%0,%1,%2,%3}, {%4,%5,%6,%7}, {%8,%9}, {%0,%1,%2,%3};" \
        : "+f"((d)[0]), "+f"((d)[1]), "+f"((d)[2]), "+f"((d)[3]) \
        : "r"((a)[0]), "r"((a)[1]), "r"((a)[2]), "r"((a)[3]), "r"(b0), "r"(b1))

// ---------------------------------------------------------------------------
// Prep A: convert [h|x] -> fp16 plane, row-major [m][k]
// ---------------------------------------------------------------------------
__global__ __launch_bounds__(256)
void prep_a(const float* __restrict__ x, const float* __restrict__ h)
{
    const int id = blockIdx.x * 256 + threadIdx.x;
    const int m  = id / 544;
    const int k  = (id % 544) * 8;
    const float* src = (k < MEMD) ? h + (size_t)m * MEMD + k
                                  : x + (size_t)m * IN_DIM + (k - MEMD);
    float4 v0 = *reinterpret_cast<const float4*>(src);
    float4 v1 = *reinterpret_cast<const float4*>(src + 4);
    float vv[8] = {v0.x, v0.y, v0.z, v0.w, v1.x, v1.y, v1.z, v1.w};
    unsigned short hs[8];
    #pragma unroll
    for (int i = 0; i < 8; i++) hs[i] = __half_as_ushort(__float2half_rn(vv[i]));
    uint4 H;
    H.x = hs[0] | ((uint32_t)hs[1] << 16);  H.y = hs[2] | ((uint32_t)hs[3] << 16);
    H.z = hs[4] | ((uint32_t)hs[5] << 16);  H.w = hs[6] | ((uint32_t)hs[7] << 16);
    *reinterpret_cast<uint4*>(g_Ah + (size_t)m * KDIM + k) = H;
}

// ---------------------------------------------------------------------------
// Prep W: transpose+concat [W1|Wd|Wu] -> fp16 plane [n][k]; pack biases
// ---------------------------------------------------------------------------
__global__ void prep_w(const float* __restrict__ W1, const float* __restrict__ Wd,
                       const float* __restrict__ Wu,
                       const float* __restrict__ b1, const float* __restrict__ bd,
                       const float* __restrict__ bu)
{
    __shared__ float t[32][33];
    const int k0 = blockIdx.x * 32, n0 = blockIdx.y * 32;
    const int tx = threadIdx.x, ty = threadIdx.y;
    const float* Wsrc; int ldw, noff;
    if (n0 < 512)      { Wsrc = W1; ldw = 512; noff = 0; }
    else if (n0 < 768) { Wsrc = Wd; ldw = 256; noff = 512; }
    else               { Wsrc = Wu; ldw = 256; noff = 768; }
    #pragma unroll
    for (int i = 0; i < 4; i++)
        t[ty + 8*i][tx] = Wsrc[(size_t)(k0 + ty + 8*i) * ldw + (n0 - noff) + tx];
    __syncthreads();
    #pragma unroll
    for (int i = 0; i < 4; i++) {
        const int n = n0 + ty + 8*i;
        g_Bh[(size_t)n * KDIM + k0 + tx] = __float2half_rn(t[tx][ty + 8*i]);
    }
    if (blockIdx.x == 0 && ty == 0) {
        const int n = n0 + tx;
        const float* bsrc = (n < 512) ? b1 : (n < 768 ? bd : bu);
        const int off = (n < 512) ? 0 : (n < 768 ? 512 : 768);
        g_ball[n] = bsrc[n - off];
    }
}

// ---------------------------------------------------------------------------
// Prep W2: transpose W2[512][256] -> g_W2t[256][512] fp16
// ---------------------------------------------------------------------------
__global__ void prep_w2(const float* __restrict__ W2)
{
    __shared__ float t[32][33];
    const int k0 = blockIdx.x * 32, n0 = blockIdx.y * 32;
    const int tx = threadIdx.x, ty = threadIdx.y;
    #pragma unroll
    for (int i = 0; i < 4; i++)
        t[ty + 8*i][tx] = W2[(size_t)(k0 + ty + 8*i) * 256 + n0 + tx];
    __syncthreads();
    #pragma unroll
    for (int i = 0; i < 4; i++)
        g_W2t[(size_t)(n0 + ty + 8*i) * 512 + k0 + tx] = __float2half_rn(t[tx][ty + 8*i]);
}

// ---------------------------------------------------------------------------
// GEMM1: BM=128, BN=256, BK=64; 512 thr; 3-stage cp.async (round-11 winner)
// ---------------------------------------------------------------------------
#define ROWB     144
#define OFF_AH   0
#define OFF_BH   18432
#define ST_BYTES 55296
#define NSTAGE   3
#define SMEM_G1  (NSTAGE * ST_BYTES)     // 162KB
#define KSTAGES  (KDIM / 64)             // 68

__global__ __launch_bounds__(512, 1)
void gemm1_mma()
{
    extern __shared__ char smem[];
    const uint32_t sb = smem_u32(smem);
    const int tid  = threadIdx.x;
    const int wid  = tid >> 5;
    const int lane = tid & 31;
    const int bx = blockIdx.x;
    const int by = blockIdx.y;

    const __half* baseA = g_Ah + (size_t)(by * 128) * KDIM;
    const __half* baseB = g_Bh + (size_t)(bx * 256) * KDIM;

    auto load_stage = [&](int s) {
        const uint32_t st = sb + (uint32_t)(s % NSTAGE) * ST_BYTES;
        const int koff = s * 64;
        #pragma unroll
        for (int t = 0; t < 6; t++) {
            const int c = t * 512 + tid;
            const __half* src;
            uint32_t dst;
            if (c < 1024) {
                const int row = c >> 3, g = c & 7;
                src = baseA + (size_t)row * KDIM + koff + g * 8;
                dst = st + OFF_AH + row * ROWB + g * 16;
            } else {
                const int c2 = c - 1024;
                const int row = c2 >> 3, g = c2 & 7;
                src = baseB + (size_t)row * KDIM + koff + g * 8;
                dst = st + OFF_BH + row * ROWB + g * 16;
            }
            CP_ASYNC16(dst, src);
        }
        CP_COMMIT();
    };

    const int wm = wid & 3;
    const int wn = wid >> 2;
    const int rsel = lane & 15;
    const int bsel = lane >> 4;

    float acc[2][8][4];
    #pragma unroll
    for (int mf = 0; mf < 2; mf++)
        #pragma unroll
        for (int nf = 0; nf < 8; nf++)
            #pragma unroll
            for (int q = 0; q < 4; q++) acc[mf][nf][q] = 0.f;

    load_stage(0);
    load_stage(1);

    #pragma unroll 1
    for (int s = 0; s < KSTAGES; s++) {
        if (s + 1 < KSTAGES) { CP_WAIT1(); } else { CP_WAIT0(); }
        __syncthreads();
        if (s + 2 < KSTAGES) load_stage(s + 2);

        const uint32_t st = sb + (uint32_t)(s % NSTAGE) * ST_BYTES;
        const uint32_t ra = (uint32_t)(wm * 32 + rsel) * ROWB;
        const uint32_t rb = (uint32_t)(wn * 64 + rsel) * ROWB;

        #pragma unroll
        for (int kk = 0; kk < 4; kk++) {
            const uint32_t kaddr = (uint32_t)(((kk << 1) + bsel) << 4);
            uint32_t Ah[2][4];
            #pragma unroll
            for (int mf = 0; mf < 2; mf++) {
                const uint32_t r = ra + (uint32_t)(mf * 16) * ROWB + kaddr;
                LDSM4(Ah[mf], st + OFF_AH + r);
            }
            #pragma unroll
            for (int j = 0; j < 4; j++) {
                uint32_t Bh[4];
                const uint32_t r = rb + (uint32_t)(j * 16) * ROWB + kaddr;
                LDSM4(Bh, st + OFF_BH + r);
                #pragma unroll
                for (int mf = 0; mf < 2; mf++)
                    #pragma unroll
                    for (int pp = 0; pp < 2; pp++)
                        MMAF16(acc[mf][j * 2 + pp], Ah[mf], Bh[pp], Bh[2 + pp]);
            }
        }
    }

    const int g  = lane >> 2;
    const int t2 = (lane & 3) * 2;
    const int ncol0 = bx * 256 + wn * 64;
    #pragma unroll
    for (int mf = 0; mf < 2; mf++) {
        const int m = by * 128 + wm * 32 + mf * 16 + g;
        float* y0 = g_Y + (size_t)m * NTOT + ncol0;
        float* y1 = y0 + (size_t)8 * NTOT;
        #pragma unroll
        for (int nf = 0; nf < 8; nf++) {
            const int nn = nf * 8 + t2;
            const float bz0 = g_ball[ncol0 + nn];
            const float bz1 = g_ball[ncol0 + nn + 1];
            *reinterpret_cast<float2*>(y0 + nn) =
                make_float2(acc[mf][nf][0] + bz0, acc[mf][nf][1] + bz1);
            *reinterpret_cast<float2*>(y1 + nn) =
                make_float2(acc[mf][nf][2] + bz0, acc[mf][nf][3] + bz1);
        }
    }
}

// ---------------------------------------------------------------------------
// fuse2_mma: LN + exact GELU -> fp16 smem; GEMM2 via HMMA (W2t fp16 staged);
// gates + liquid update + L2 renorm. 64 rows/block, grid 128, 256 thr.
// ---------------------------------------------------------------------------
#define TROW    1040                     // 512 halfs + 8 pad
#define F2_T    0                        // 64*1040 = 66560
#define W2ROW   144
#define W2_ST   36864                    // 256*144
#define F2_W2   66560                    // 3 stages
#define F2_H2   177152                   // 64 floats
#define F2_N2   177408                   // 64*4 floats
#define F2_SC   178432                   // 64 floats
#define SMEM_F2 178688

__global__ __launch_bounds__(256, 1)
void fuse2_mma(const float* __restrict__ h,
               const float* __restrict__ gam, const float* __restrict__ bet,
               const float* __restrict__ b2, float* __restrict__ out)
{
    extern __shared__ char smem[];
    const uint32_t sb = smem_u32(smem);
    float* s_h2 = reinterpret_cast<float*>(smem + F2_H2);
    float* s_n2 = reinterpret_cast<float*>(smem + F2_N2);
    float* s_sc = reinterpret_cast<float*>(smem + F2_SC);

    const int tid  = threadIdx.x;
    const int wid  = tid >> 5;
    const int lane = tid & 31;
    const int row0 = blockIdx.x * 64;

    // W2t stage loader: 256 rows x 128B per stage -> 2048 chunks, 8/thread
    auto load_w2 = [&](int s) {
        const uint32_t st = sb + F2_W2 + (uint32_t)(s % 3) * W2_ST;
        const int koff = s * 64;
        #pragma unroll
        for (int t = 0; t < 8; t++) {
            const int c = t * 256 + tid;
            const int n = c >> 3, g = c & 7;
            const __half* src = g_W2t + (size_t)n * 512 + koff + g * 8;
            CP_ASYNC16(st + n * W2ROW + g * 16, src);
        }
        CP_COMMIT();
    };
    load_w2(0);
    load_w2(1);

    // ---- Phase A: LN + GELU -> fp16 smem; per-row ||h||^2. 8 rows/warp.
    const int wrow = wid * 8;
    #pragma unroll 1
    for (int i = 0; i < 8; i++) {
        const int r = wrow + i;
        const float* yrow = g_Y + (size_t)(row0 + r) * NTOT;
        float vals[16];
        float s = 0.f, s2 = 0.f;
        #pragma unroll
        for (int q = 0; q < 4; q++) {
            float4 v = *reinterpret_cast<const float4*>(yrow + (lane + q * 32) * 4);
            vals[q*4+0] = v.x; vals[q*4+1] = v.y; vals[q*4+2] = v.z; vals[q*4+3] = v.w;
            s  += v.x + v.y + v.z + v.w;
            s2 += v.x*v.x + v.y*v.y + v.z*v.z + v.w*v.w;
        }
        #pragma unroll
        for (int o = 16; o; o >>= 1) {
            s  += __shfl_xor_sync(0xffffffffu, s,  o);
            s2 += __shfl_xor_sync(0xffffffffu, s2, o);
        }
        const float mu   = s * (1.f / 512.f);
        const float var  = s2 * (1.f / 512.f) - mu * mu;
        const float rstd = rsqrtf(var + 1e-5f);
        #pragma unroll
        for (int q = 0; q < 4; q++) {
            const int c = (lane + q * 32) * 4;
            float4 gv = *reinterpret_cast<const float4*>(gam + c);
            float4 bv = *reinterpret_cast<const float4*>(bet + c);
            float gl[4];
            float g4[4]  = {gv.x, gv.y, gv.z, gv.w};
            float be4[4] = {bv.x, bv.y, bv.z, bv.w};
            #pragma unroll
            for (int e = 0; e < 4; e++) {
                float t = (vals[q*4+e] - mu) * rstd * g4[e] + be4[e];
                gl[e] = 0.5f * t * (1.f + erff(t * 0.7071067811865475f));
            }
            uint32_t u0 = __half_as_ushort(__float2half_rn(gl[0])) |
                          ((uint32_t)__half_as_ushort(__float2half_rn(gl[1])) << 16);
            uint32_t u1 = __half_as_ushort(__float2half_rn(gl[2])) |
                          ((uint32_t)__half_as_ushort(__float2half_rn(gl[3])) << 16);
            asm volatile("st.shared.v2.b32 [%0], {%1, %2};"
                :: "r"(sb + F2_T + (uint32_t)r * TROW + (uint32_t)c * 2), "r"(u0), "r"(u1)
                : "memory");
        }
        // ||h||^2 for this row
        const float* hrow = h + (size_t)(row0 + r) * MEMD;
        float4 a0 = *reinterpret_cast<const float4*>(hrow + lane * 8);
        float4 a1 = *reinterpret_cast<const float4*>(hrow + lane * 8 + 4);
        float hh = a0.x*a0.x + a0.y*a0.y + a0.z*a0.z + a0.w*a0.w
                 + a1.x*a1.x + a1.y*a1.y + a1.z*a1.z + a1.w*a1.w;
        #pragma unroll
        for (int o = 16; o; o >>= 1) hh += __shfl_xor_sync(0xffffffffu, hh, o);
        if (lane == 0) s_h2[r] = hh;
    }

    // ---- Phase B: MMA GEMM2 (64x256x512), warp grid 2m x 4n, tile 32x64
    const int wm = wid >> 2;
    const int wn = wid & 3;
    const int rsel = lane & 15;
    const int bsel = lane >> 4;

    float acc[2][8][4];
    #pragma unroll
    for (int mf = 0; mf < 2; mf++)
        #pragma unroll
        for (int nf = 0; nf < 8; nf++)
            #pragma unroll
            for (int q = 0; q < 4; q++) acc[mf][nf][q] = 0.f;

    #pragma unroll 1
    for (int s = 0; s < 8; s++) {
        if (s < 7) { CP_WAIT1(); } else { CP_WAIT0(); }
        __syncthreads();
        if (s + 2 < 8) load_w2(s + 2);

        const uint32_t stw = sb + F2_W2 + (uint32_t)(s % 3) * W2_ST;
        const uint32_t ta  = sb + F2_T + (uint32_t)(s * 128);
        const uint32_t ra  = (uint32_t)(wm * 32 + rsel) * TROW;
        const uint32_t rb  = (uint32_t)(wn * 64 + rsel) * W2ROW;

        #pragma unroll
        for (int kk = 0; kk < 4; kk++) {
            const uint32_t kaddr = (uint32_t)(((kk << 1) + bsel) << 4);
            uint32_t Ah[2][4];
            #pragma unroll
            for (int mf = 0; mf < 2; mf++)
                LDSM4(Ah[mf], ta + ra + (uint32_t)(mf * 16) * TROW + kaddr);
            #pragma unroll
            for (int j = 0; j < 4; j++) {
                uint32_t Bh[4];
                LDSM4(Bh, stw + rb + (uint32_t)(j * 16) * W2ROW + kaddr);
                #pragma unroll
                for (int mf = 0; mf < 2; mf++)
                    #pragma unroll
                    for (int pp = 0; pp < 2; pp++)
                        MMAF16(acc[mf][j * 2 + pp], Ah[mf], Bh[pp], Bh[2 + pp]);
            }
        }
    }

    // ---- Phase C: gates + liquid update + renorm
    const int g  = lane >> 2;
    const int t2 = (lane & 3) * 2;
    float nh2[2][2] = {{0.f, 0.f}, {0.f, 0.f}};

    #pragma unroll
    for (int mf = 0; mf < 2; mf++) {
        const int r1 = wm * 32 + mf * 16 + g;
        const int rg1 = row0 + r1, rg2 = rg1 + 8;
        const float* y1 = g_Y + (size_t)rg1 * NTOT;
        const float* y2 = g_Y + (size_t)rg2 * NTOT;
        const float* h1 = h + (size_t)rg1 * MEMD;
        const float* h2p = h + (size_t)rg2 * MEMD;
        #pragma unroll
        for (int nf = 0; nf < 8; nf++) {
            const int j0 = wn * 64 + nf * 8 + t2;
            const float bz0 = b2[j0], bz1 = b2[j0 + 1];
            float2 d1 = *reinterpret_cast<const float2*>(y1 + 512 + j0);
            float2 u1 = *reinterpret_cast<const float2*>(y1 + 768 + j0);
            float2 d2 = *reinterpret_cast<const float2*>(y2 + 512 + j0);
            float2 u2 = *reinterpret_cast<const float2*>(y2 + 768 + j0);
            float2 hv1 = *reinterpret_cast<const float2*>(h1 + j0);
            float2 hv2 = *reinterpret_cast<const float2*>(h2p + j0);

            float hc, dec, ts, uu, nh;
            hc = tanhf(acc[mf][nf][0] + bz0);
            dec = 1.f / (1.f + __expf(-d1.x)); ts = 0.1f + 9.9f * dec + 1e-6f;
            uu  = 1.f / (1.f + __expf(-u1.x));
            nh = (1.f - uu) * (hv1.x / ts) + uu * hc;
            acc[mf][nf][0] = nh; nh2[mf][0] += nh * nh;

            hc = tanhf(acc[mf][nf][1] + bz1);
            dec = 1.f / (1.f + __expf(-d1.y)); ts = 0.1f + 9.9f * dec + 1e-6f;
            uu  = 1.f / (1.f + __expf(-u1.y));
            nh = (1.f - uu) * (hv1.y / ts) + uu * hc;
            acc[mf][nf][1] = nh; nh2[mf][0] += nh * nh;

            hc = tanhf(acc[mf][nf][2] + bz0);
            dec = 1.f / (1.f + __expf(-d2.x)); ts = 0.1f + 9.9f * dec + 1e-6f;
            uu  = 1.f / (1.f + __expf(-u2.x));
            nh = (1.f - uu) * (hv2.x / ts) + uu * hc;
            acc[mf][nf][2] = nh; nh2[mf][1] += nh * nh;

            hc = tanhf(acc[mf][nf][3] + bz1);
            dec = 1.f / (1.f + __expf(-d2.y)); ts = 0.1f + 9.9f * dec + 1e-6f;
            uu  = 1.f / (1.f + __expf(-u2.y));
            nh = (1.f - uu) * (hv2.y / ts) + uu * hc;
            acc[mf][nf][3] = nh; nh2[mf][1] += nh * nh;
        }
    }

    // quad-reduce over lanes sharing a row (t2 varies within quad)
    #pragma unroll
    for (int mf = 0; mf < 2; mf++)
        #pragma unroll
        for (int hh = 0; hh < 2; hh++) {
            float v = nh2[mf][hh];
            v += __shfl_xor_sync(0xffffffffu, v, 1);
            v += __shfl_xor_sync(0xffffffffu, v, 2);
            if ((lane & 3) == 0)
                s_n2[(wm * 32 + mf * 16 + g + hh * 8) * 4 + wn] = v;
        }
    __syncthreads();

    if (tid < 64) {
        float n2 = s_n2[tid * 4 + 0] + s_n2[tid * 4 + 1]
                 + s_n2[tid * 4 + 2] + s_n2[tid * 4 + 3];
        s_sc[tid] = fmaxf(sqrtf(s_h2[tid]), 1e-6f) / fmaxf(sqrtf(n2), 1e-12f);
    }
    __syncthreads();

    #pragma unroll
    for (int mf = 0; mf < 2; mf++) {
        const int r1 = wm * 32 + mf * 16 + g;
        const float sc1 = s_sc[r1], sc2 = s_sc[r1 + 8];
        float* o1 = out + (size_t)(row0 + r1) * MEMD;
        float* o2 = out + (size_t)(row0 + r1 + 8) * MEMD;
        #pragma unroll
        for (int nf = 0; nf < 8; nf++) {
            const int j0 = wn * 64 + nf * 8 + t2;
            *reinterpret_cast<float2*>(o1 + j0) =
                make_float2(acc[mf][nf][0] * sc1, acc[mf][nf][1] * sc1);
            *reinterpret_cast<float2*>(o2 + j0) =
                make_float2(acc[mf][nf][2] * sc2, acc[mf][nf][3] * sc2);
        }
    }
}

// ---------------------------------------------------------------------------
extern "C" void kernel_launch(void* const* d_in, const int* in_sizes, int n_in,
                              void* d_out, int out_size)
{
    (void)in_sizes; (void)n_in; (void)out_size;
    const float* x   = (const float*)d_in[0];
    const float* h   = (const float*)d_in[1];
    const float* W1  = (const float*)d_in[2];
    const float* b1  = (const float*)d_in[3];
    const float* gam = (const float*)d_in[4];
    const float* bet = (const float*)d_in[5];
    const float* W2  = (const float*)d_in[6];
    const float* b2  = (const float*)d_in[7];
    const float* Wd  = (const float*)d_in[8];
    const float* bd  = (const float*)d_in[9];
    const float* Wu  = (const float*)d_in[10];
    const float* bu  = (const float*)d_in[11];
    float* out = (float*)d_out;

    cudaFuncSetAttribute(gemm1_mma, cudaFuncAttributeMaxDynamicSharedMemorySize, SMEM_G1);
    cudaFuncSetAttribute(fuse2_mma, cudaFuncAttributeMaxDynamicSharedMemorySize, SMEM_F2);

    prep_a<<<(BATCH * (KDIM / 8)) / 256, 256>>>(x, h);
    prep_w<<<dim3(KDIM / 32, NTOT / 32), dim3(32, 8)>>>(W1, Wd, Wu, b1, bd, bu);
    prep_w2<<<dim3(16, 8), dim3(32, 8)>>>(W2);

    dim3 ggrid(NTOT / 256, BATCH / 128);
    gemm1_mma<<<ggrid, 512, SMEM_G1>>>();

    fuse2_mma<<<BATCH / 64, 256, SMEM_F2>>>(h, gam, bet, b2, out);
}

// round 16
// speedup vs baseline: 2.6420x; 1.0028x over previous
#include <cuda_runtime.h>
#include <cuda_fp16.h>
#include <math.h>
#include <cstdint>

#define BATCH  8192
#define IN_DIM 4096
#define MEMD   256
#define KDIM   4352
#define NTOT   1024

// gmem scratch (fp16 planes)
__device__ float  g_Y  [(size_t)BATCH * NTOT];
__device__ __half g_Ah [(size_t)BATCH * KDIM];
__device__ __half g_Bh [(size_t)NTOT  * KDIM];
__device__ __half g_W2t[(size_t)MEMD * 512];
__device__ float  g_ball[NTOT];

// ------------------------------- helpers ----------------------------------
__device__ __forceinline__ uint32_t smem_u32(const void* p){
    uint32_t a;
    asm("{ .reg .u64 t; cvta.to.shared.u64 t, %1; cvt.u32.u64 %0, t; }" : "=r"(a) : "l"(p));
    return a;
}

#define CP_ASYNC16(dst, src) \
    asm volatile("cp.async.cg.shared.global [%0], [%1], 16;" :: "r"(dst), "l"(src))
#define CP_COMMIT() asm volatile("cp.async.commit_group;" ::: "memory")
#define CP_WAIT1()  asm volatile("cp.async.wait_group 1;" ::: "memory")
#define CP_WAIT0()  asm volatile("cp.async.wait_group 0;" ::: "memory")

#define LDSM4(r, addr) \
    asm volatile("ldmatrix.sync.aligned.m8n8.x4.shared.b16 {%0,%1,%2,%3}, [%4];" \
        : "=r"((r)[0]), "=r"((r)[1]), "=r"((r)[2]), "=r"((r)[3]) : "r"(addr))

#define MMAF16(d, a, b0, b1) \
    asm volatile("mma.sync.aligned.m16n8k16.row.col.f32.f16.f16.f32 " \
        "{%0,%1,%2,%3}, {%4,%5,%6,%7}, {%8,%9}, {%0,%1,%2,%3};" \
        : "+f"((d)[0]), "+f"((d)[1]), "+f"((d)[2]), "+f"((d)[3]) \
        : "r"((a)[0]), "r"((a)[1]), "r"((a)[2]), "r"((a)[3]), "r"(b0), "r"(b1))

// ---------------------------------------------------------------------------
// Prep A: convert [h|x] -> fp16 plane, row-major [m][k]
// ---------------------------------------------------------------------------
__global__ __launch_bounds__(256)
void prep_a(const float* __restrict__ x, const float* __restrict__ h)
{
    const int id = blockIdx.x * 256 + threadIdx.x;
    const int m  = id / 544;
    const int k  = (id % 544) * 8;
    const float* src = (k < MEMD) ? h + (size_t)m * MEMD + k
                                  : x + (size_t)m * IN_DIM + (k - MEMD);
    float4 v0 = *reinterpret_cast<const float4*>(src);
    float4 v1 = *reinterpret_cast<const float4*>(src + 4);
    float vv[8] = {v0.x, v0.y, v0.z, v0.w, v1.x, v1.y, v1.z, v1.w};
    unsigned short hs[8];
    #pragma unroll
    for (int i = 0; i < 8; i++) hs[i] = __half_as_ushort(__float2half_rn(vv[i]));
    uint4 H;
    H.x = hs[0] | ((uint32_t)hs[1] << 16);  H.y = hs[2] | ((uint32_t)hs[3] << 16);
    H.z = hs[4] | ((uint32_t)hs[5] << 16);  H.w = hs[6] | ((uint32_t)hs[7] << 16);
    *reinterpret_cast<uint4*>(g_Ah + (size_t)m * KDIM + k) = H;
}

// ---------------------------------------------------------------------------
// Prep W: transpose+concat [W1|Wd|Wu] -> fp16 plane [n][k]; pack biases
// ---------------------------------------------------------------------------
__global__ void prep_w(const float* __restrict__ W1, const float* __restrict__ Wd,
                       const float* __restrict__ Wu,
                       const float* __restrict__ b1, const float* __restrict__ bd,
                       const float* __restrict__ bu)
{
    __shared__ float t[32][33];
    const int k0 = blockIdx.x * 32, n0 = blockIdx.y * 32;
    const int tx = threadIdx.x, ty = threadIdx.y;
    const float* Wsrc; int ldw, noff;
    if (n0 < 512)      { Wsrc = W1; ldw = 512; noff = 0; }
    else if (n0 < 768) { Wsrc = Wd; ldw = 256; noff = 512; }
    else               { Wsrc = Wu; ldw = 256; noff = 768; }
    #pragma unroll
    for (int i = 0; i < 4; i++)
        t[ty + 8*i][tx] = Wsrc[(size_t)(k0 + ty + 8*i) * ldw + (n0 - noff) + tx];
    __syncthreads();
    #pragma unroll
    for (int i = 0; i < 4; i++) {
        const int n = n0 + ty + 8*i;
        g_Bh[(size_t)n * KDIM + k0 + tx] = __float2half_rn(t[tx][ty + 8*i]);
    }
    if (blockIdx.x == 0 && ty == 0) {
        const int n = n0 + tx;
        const float* bsrc = (n < 512) ? b1 : (n < 768 ? bd : bu);
        const int off = (n < 512) ? 0 : (n < 768 ? 512 : 768);
        g_ball[n] = bsrc[n - off];
    }
}

// ---------------------------------------------------------------------------
// Prep W2: transpose W2[512][256] -> g_W2t[256][512] fp16
// ---------------------------------------------------------------------------
__global__ void prep_w2(const float* __restrict__ W2)
{
    __shared__ float t[32][33];
    const int k0 = blockIdx.x * 32, n0 = blockIdx.y * 32;
    const int tx = threadIdx.x, ty = threadIdx.y;
    #pragma unroll
    for (int i = 0; i < 4; i++)
        t[ty + 8*i][tx] = W2[(size_t)(k0 + ty + 8*i) * 256 + n0 + tx];
    __syncthreads();
    #pragma unroll
    for (int i = 0; i < 4; i++)
        g_W2t[(size_t)(n0 + ty + 8*i) * 512 + k0 + tx] = __float2half_rn(t[tx][ty + 8*i]);
}

// ---------------------------------------------------------------------------
// GEMM1: BM=128, BN=256, BK=64; 512 thr; 3-stage cp.async;
// ALL fragments (A+B) hoisted per kk before the MMA block.
// ---------------------------------------------------------------------------
#define ROWB     144
#define OFF_AH   0
#define OFF_BH   18432
#define ST_BYTES 55296
#define NSTAGE   3
#define SMEM_G1  (NSTAGE * ST_BYTES)     // 162KB
#define KSTAGES  (KDIM / 64)             // 68

__global__ __launch_bounds__(512, 1)
void gemm1_mma()
{
    extern __shared__ char smem[];
    const uint32_t sb = smem_u32(smem);
    const int tid  = threadIdx.x;
    const int wid  = tid >> 5;
    const int lane = tid & 31;
    const int bx = blockIdx.x;
    const int by = blockIdx.y;

    const __half* baseA = g_Ah + (size_t)(by * 128) * KDIM;
    const __half* baseB = g_Bh + (size_t)(bx * 256) * KDIM;

    auto load_stage = [&](int s) {
        const uint32_t st = sb + (uint32_t)(s % NSTAGE) * ST_BYTES;
        const int koff = s * 64;
        #pragma unroll
        for (int t = 0; t < 6; t++) {
            const int c = t * 512 + tid;
            const __half* src;
            uint32_t dst;
            if (c < 1024) {
                const int row = c >> 3, g = c & 7;
                src = baseA + (size_t)row * KDIM + koff + g * 8;
                dst = st + OFF_AH + row * ROWB + g * 16;
            } else {
                const int c2 = c - 1024;
                const int row = c2 >> 3, g = c2 & 7;
                src = baseB + (size_t)row * KDIM + koff + g * 8;
                dst = st + OFF_BH + row * ROWB + g * 16;
            }
            CP_ASYNC16(dst, src);
        }
        CP_COMMIT();
    };

    const int wm = wid & 3;
    const int wn = wid >> 2;
    const int rsel = lane & 15;
    const int bsel = lane >> 4;

    float acc[2][8][4];
    #pragma unroll
    for (int mf = 0; mf < 2; mf++)
        #pragma unroll
        for (int nf = 0; nf < 8; nf++)
            #pragma unroll
            for (int q = 0; q < 4; q++) acc[mf][nf][q] = 0.f;

    load_stage(0);
    load_stage(1);

    #pragma unroll 1
    for (int s = 0; s < KSTAGES; s++) {
        if (s + 1 < KSTAGES) { CP_WAIT1(); } else { CP_WAIT0(); }
        __syncthreads();
        if (s + 2 < KSTAGES) load_stage(s + 2);

        const uint32_t st = sb + (uint32_t)(s % NSTAGE) * ST_BYTES;
        const uint32_t ra = st + OFF_AH + (uint32_t)(wm * 32 + rsel) * ROWB;
        const uint32_t rb = st + OFF_BH + (uint32_t)(wn * 64 + rsel) * ROWB;

        #pragma unroll
        for (int kk = 0; kk < 4; kk++) {
            const uint32_t kaddr = (uint32_t)(((kk << 1) + bsel) << 4);
            uint32_t Ah[2][4], Bh[4][4];
            // hoist ALL loads for this kk — no MMA interleaved
            #pragma unroll
            for (int mf = 0; mf < 2; mf++)
                LDSM4(Ah[mf], ra + (uint32_t)(mf * 16) * ROWB + kaddr);
            #pragma unroll
            for (int j = 0; j < 4; j++)
                LDSM4(Bh[j], rb + (uint32_t)(j * 16) * ROWB + kaddr);
            // dependency-free MMA block
            #pragma unroll
            for (int j = 0; j < 4; j++)
                #pragma unroll
                for (int mf = 0; mf < 2; mf++)
                    #pragma unroll
                    for (int pp = 0; pp < 2; pp++)
                        MMAF16(acc[mf][j * 2 + pp], Ah[mf], Bh[j][pp], Bh[j][2 + pp]);
        }
    }

    const int g  = lane >> 2;
    const int t2 = (lane & 3) * 2;
    const int ncol0 = bx * 256 + wn * 64;
    #pragma unroll
    for (int mf = 0; mf < 2; mf++) {
        const int m = by * 128 + wm * 32 + mf * 16 + g;
        float* y0 = g_Y + (size_t)m * NTOT + ncol0;
        float* y1 = y0 + (size_t)8 * NTOT;
        #pragma unroll
        for (int nf = 0; nf < 8; nf++) {
            const int nn = nf * 8 + t2;
            const float bz0 = g_ball[ncol0 + nn];
            const float bz1 = g_ball[ncol0 + nn + 1];
            *reinterpret_cast<float2*>(y0 + nn) =
                make_float2(acc[mf][nf][0] + bz0, acc[mf][nf][1] + bz1);
            *reinterpret_cast<float2*>(y1 + nn) =
                make_float2(acc[mf][nf][2] + bz0, acc[mf][nf][3] + bz1);
        }
    }
}

// ---------------------------------------------------------------------------
// fuse2_mma: LN + exact GELU -> fp16 smem; GEMM2 via HMMA; gates + renorm.
// 64 rows/block, grid 128, 256 thr. Fragments hoisted like gemm1.
// ---------------------------------------------------------------------------
#define TROW    1040
#define F2_T    0
#define W2ROW   144
#define W2_ST   36864
#define F2_W2   66560
#define F2_H2   177152
#define F2_N2   177408
#define F2_SC   178432
#define SMEM_F2 178688

__global__ __launch_bounds__(256, 1)
void fuse2_mma(const float* __restrict__ h,
               const float* __restrict__ gam, const float* __restrict__ bet,
               const float* __restrict__ b2, float* __restrict__ out)
{
    extern __shared__ char smem[];
    const uint32_t sb = smem_u32(smem);
    float* s_h2 = reinterpret_cast<float*>(smem + F2_H2);
    float* s_n2 = reinterpret_cast<float*>(smem + F2_N2);
    float* s_sc = reinterpret_cast<float*>(smem + F2_SC);

    const int tid  = threadIdx.x;
    const int wid  = tid >> 5;
    const int lane = tid & 31;
    const int row0 = blockIdx.x * 64;

    auto load_w2 = [&](int s) {
        const uint32_t st = sb + F2_W2 + (uint32_t)(s % 3) * W2_ST;
        const int koff = s * 64;
        #pragma unroll
        for (int t = 0; t < 8; t++) {
            const int c = t * 256 + tid;
            const int n = c >> 3, g = c & 7;
            const __half* src = g_W2t + (size_t)n * 512 + koff + g * 8;
            CP_ASYNC16(st + n * W2ROW + g * 16, src);
        }
        CP_COMMIT();
    };
    load_w2(0);
    load_w2(1);

    // ---- Phase A: LN + GELU -> fp16 smem; per-row ||h||^2. 8 rows/warp.
    const int wrow = wid * 8;
    #pragma unroll 1
    for (int i = 0; i < 8; i++) {
        const int r = wrow + i;
        const float* yrow = g_Y + (size_t)(row0 + r) * NTOT;
        float vals[16];
        float s = 0.f, s2 = 0.f;
        #pragma unroll
        for (int q = 0; q < 4; q++) {
            float4 v = *reinterpret_cast<const float4*>(yrow + (lane + q * 32) * 4);
            vals[q*4+0] = v.x; vals[q*4+1] = v.y; vals[q*4+2] = v.z; vals[q*4+3] = v.w;
            s  += v.x + v.y + v.z + v.w;
            s2 += v.x*v.x + v.y*v.y + v.z*v.z + v.w*v.w;
        }
        #pragma unroll
        for (int o = 16; o; o >>= 1) {
            s  += __shfl_xor_sync(0xffffffffu, s,  o);
            s2 += __shfl_xor_sync(0xffffffffu, s2, o);
        }
        const float mu   = s * (1.f / 512.f);
        const float var  = s2 * (1.f / 512.f) - mu * mu;
        const float rstd = rsqrtf(var + 1e-5f);
        #pragma unroll
        for (int q = 0; q < 4; q++) {
            const int c = (lane + q * 32) * 4;
            float4 gv = *reinterpret_cast<const float4*>(gam + c);
            float4 bv = *reinterpret_cast<const float4*>(bet + c);
            float gl[4];
            float g4[4]  = {gv.x, gv.y, gv.z, gv.w};
            float be4[4] = {bv.x, bv.y, bv.z, bv.w};
            #pragma unroll
            for (int e = 0; e < 4; e++) {
                float t = (vals[q*4+e] - mu) * rstd * g4[e] + be4[e];
                gl[e] = 0.5f * t * (1.f + erff(t * 0.7071067811865475f));
            }
            uint32_t u0 = __half_as_ushort(__float2half_rn(gl[0])) |
                          ((uint32_t)__half_as_ushort(__float2half_rn(gl[1])) << 16);
            uint32_t u1 = __half_as_ushort(__float2half_rn(gl[2])) |
                          ((uint32_t)__half_as_ushort(__float2half_rn(gl[3])) << 16);
            asm volatile("st.shared.v2.b32 [%0], {%1, %2};"
                :: "r"(sb + F2_T + (uint32_t)r * TROW + (uint32_t)c * 2), "r"(u0), "r"(u1)
                : "memory");
        }
        const float* hrow = h + (size_t)(row0 + r) * MEMD;
        float4 a0 = *reinterpret_cast<const float4*>(hrow + lane * 8);
        float4 a1 = *reinterpret_cast<const float4*>(hrow + lane * 8 + 4);
        float hh = a0.x*a0.x + a0.y*a0.y + a0.z*a0.z + a0.w*a0.w
                 + a1.x*a1.x + a1.y*a1.y + a1.z*a1.z + a1.w*a1.w;
        #pragma unroll
        for (int o = 16; o; o >>= 1) hh += __shfl_xor_sync(0xffffffffu, hh, o);
        if (lane == 0) s_h2[r] = hh;
    }

    // ---- Phase B: MMA GEMM2 (64x256x512), warp grid 2m x 4n
    const int wm = wid >> 2;
    const int wn = wid & 3;
    const int rsel = lane & 15;
    const int bsel = lane >> 4;

    float acc[2][8][4];
    #pragma unroll
    for (int mf = 0; mf < 2; mf++)
        #pragma unroll
        for (int nf = 0; nf < 8; nf++)
            #pragma unroll
            for (int q = 0; q < 4; q++) acc[mf][nf][q] = 0.f;

    #pragma unroll 1
    for (int s = 0; s < 8; s++) {
        if (s < 7) { CP_WAIT1(); } else { CP_WAIT0(); }
        __syncthreads();
        if (s + 2 < 8) load_w2(s + 2);

        const uint32_t stw = sb + F2_W2 + (uint32_t)(s % 3) * W2_ST;
        const uint32_t ta  = sb + F2_T + (uint32_t)(s * 128) + (uint32_t)(wm * 32 + rsel) * TROW;
        const uint32_t rb  = stw + (uint32_t)(wn * 64 + rsel) * W2ROW;

        #pragma unroll
        for (int kk = 0; kk < 4; kk++) {
            const uint32_t kaddr = (uint32_t)(((kk << 1) + bsel) << 4);
            uint32_t Ah[2][4], Bh[4][4];
            #pragma unroll
            for (int mf = 0; mf < 2; mf++)
                LDSM4(Ah[mf], ta + (uint32_t)(mf * 16) * TROW + kaddr);
            #pragma unroll
            for (int j = 0; j < 4; j++)
                LDSM4(Bh[j], rb + (uint32_t)(j * 16) * W2ROW + kaddr);
            #pragma unroll
            for (int j = 0; j < 4; j++)
                #pragma unroll
                for (int mf = 0; mf < 2; mf++)
                    #pragma unroll
                    for (int pp = 0; pp < 2; pp++)
                        MMAF16(acc[mf][j * 2 + pp], Ah[mf], Bh[j][pp], Bh[j][2 + pp]);
        }
    }

    // ---- Phase C: gates + liquid update + renorm
    const int g  = lane >> 2;
    const int t2 = (lane & 3) * 2;
    float nh2[2][2] = {{0.f, 0.f}, {0.f, 0.f}};

    #pragma unroll
    for (int mf = 0; mf < 2; mf++) {
        const int r1 = wm * 32 + mf * 16 + g;
        const int rg1 = row0 + r1, rg2 = rg1 + 8;
        const float* y1 = g_Y + (size_t)rg1 * NTOT;
        const float* y2 = g_Y + (size_t)rg2 * NTOT;
        const float* h1 = h + (size_t)rg1 * MEMD;
        const float* h2p = h + (size_t)rg2 * MEMD;
        #pragma unroll
        for (int nf = 0; nf < 8; nf++) {
            const int j0 = wn * 64 + nf * 8 + t2;
            const float bz0 = b2[j0], bz1 = b2[j0 + 1];
            float2 d1 = *reinterpret_cast<const float2*>(y1 + 512 + j0);
            float2 u1 = *reinterpret_cast<const float2*>(y1 + 768 + j0);
            float2 d2 = *reinterpret_cast<const float2*>(y2 + 512 + j0);
            float2 u2 = *reinterpret_cast<const float2*>(y2 + 768 + j0);
            float2 hv1 = *reinterpret_cast<const float2*>(h1 + j0);
            float2 hv2 = *reinterpret_cast<const float2*>(h2p + j0);

            float hc, dec, ts, uu, nh;
            hc = tanhf(acc[mf][nf][0] + bz0);
            dec = 1.f / (1.f + __expf(-d1.x)); ts = 0.1f + 9.9f * dec + 1e-6f;
            uu  = 1.f / (1.f + __expf(-u1.x));
            nh = (1.f - uu) * (hv1.x / ts) + uu * hc;
            acc[mf][nf][0] = nh; nh2[mf][0] += nh * nh;

            hc = tanhf(acc[mf][nf][1] + bz1);
            dec = 1.f / (1.f + __expf(-d1.y)); ts = 0.1f + 9.9f * dec + 1e-6f;
            uu  = 1.f / (1.f + __expf(-u1.y));
            nh = (1.f - uu) * (hv1.y / ts) + uu * hc;
            acc[mf][nf][1] = nh; nh2[mf][0] += nh * nh;

            hc = tanhf(acc[mf][nf][2] + bz0);
            dec = 1.f / (1.f + __expf(-d2.x)); ts = 0.1f + 9.9f * dec + 1e-6f;
            uu  = 1.f / (1.f + __expf(-u2.x));
            nh = (1.f - uu) * (hv2.x / ts) + uu * hc;
            acc[mf][nf][2] = nh; nh2[mf][1] += nh * nh;

            hc = tanhf(acc[mf][nf][3] + bz1);
            dec = 1.f / (1.f + __expf(-d2.y)); ts = 0.1f + 9.9f * dec + 1e-6f;
            uu  = 1.f / (1.f + __expf(-u2.y));
            nh = (1.f - uu) * (hv2.y / ts) + uu * hc;
            acc[mf][nf][3] = nh; nh2[mf][1] += nh * nh;
        }
    }

    #pragma unroll
    for (int mf = 0; mf < 2; mf++)
        #pragma unroll
        for (int hh = 0; hh < 2; hh++) {
            float v = nh2[mf][hh];
            v += __shfl_xor_sync(0xffffffffu, v, 1);
            v += __shfl_xor_sync(0xffffffffu, v, 2);
            if ((lane & 3) == 0)
                s_n2[(wm * 32 + mf * 16 + g + hh * 8) * 4 + wn] = v;
        }
    __syncthreads();

    if (tid < 64) {
        float n2 = s_n2[tid * 4 + 0] + s_n2[tid * 4 + 1]
                 + s_n2[tid * 4 + 2] + s_n2[tid * 4 + 3];
        s_sc[tid] = fmaxf(sqrtf(s_h2[tid]), 1e-6f) / fmaxf(sqrtf(n2), 1e-12f);
    }
    __syncthreads();

    #pragma unroll
    for (int mf = 0; mf < 2; mf++) {
        const int r1 = wm * 32 + mf * 16 + g;
        const float sc1 = s_sc[r1], sc2 = s_sc[r1 + 8];
        float* o1 = out + (size_t)(row0 + r1) * MEMD;
        float* o2 = out + (size_t)(row0 + r1 + 8) * MEMD;
        #pragma unroll
        for (int nf = 0; nf < 8; nf++) {
            const int j0 = wn * 64 + nf * 8 + t2;
            *reinterpret_cast<float2*>(o1 + j0) =
                make_float2(acc[mf][nf][0] * sc1, acc[mf][nf][1] * sc1);
            *reinterpret_cast<float2*>(o2 + j0) =
                make_float2(acc[mf][nf][2] * sc2, acc[mf][nf][3] * sc2);
        }
    }
}

// ---------------------------------------------------------------------------
extern "C" void kernel_launch(void* const* d_in, const int* in_sizes, int n_in,
                              void* d_out, int out_size)
{
    (void)in_sizes; (void)n_in; (void)out_size;
    const float* x   = (const float*)d_in[0];
    const float* h   = (const float*)d_in[1];
    const float* W1  = (const float*)d_in[2];
    const float* b1  = (const float*)d_in[3];
    const float* gam = (const float*)d_in[4];
    const float* bet = (const float*)d_in[5];
    const float* W2  = (const float*)d_in[6];
    const float* b2  = (const float*)d_in[7];
    const float* Wd  = (const float*)d_in[8];
    const float* bd  = (const float*)d_in[9];
    const float* Wu  = (const float*)d_in[10];
    const float* bu  = (const float*)d_in[11];
    float* out = (float*)d_out;

    cudaFuncSetAttribute(gemm1_mma, cudaFuncAttributeMaxDynamicSharedMemorySize, SMEM_G1);
    cudaFuncSetAttribute(fuse2_mma, cudaFuncAttributeMaxDynamicSharedMemorySize, SMEM_F2);

    prep_a<<<(BATCH * (KDIM / 8)) / 256, 256>>>(x, h);
    prep_w<<<dim3(KDIM / 32, NTOT / 32), dim3(32, 8)>>>(W1, Wd, Wu, b1, bd, bu);
    prep_w2<<<dim3(16, 8), dim3(32, 8)>>>(W2);

    dim3 ggrid(NTOT / 256, BATCH / 128);
    gemm1_mma<<<ggrid, 512, SMEM_G1>>>();

    fuse2_mma<<<BATCH / 64, 256, SMEM_F2>>>(h, gam, bet, b2, out);
}

// round 17
// speedup vs baseline: 2.6586x; 1.0063x over previous
#include <cuda_runtime.h>
#include <cuda_fp16.h>
#include <math.h>
#include <cstdint>

#define BATCH  8192
#define IN_DIM 4096
#define MEMD   256
#define KDIM   4352
#define NTOT   1024

// gmem scratch (fp16 planes)
__device__ float  g_Y  [(size_t)BATCH * NTOT];
__device__ __half g_Ah [(size_t)BATCH * KDIM];
__device__ __half g_Bh [(size_t)NTOT  * KDIM];
__device__ __half g_W2t[(size_t)MEMD * 512];
__device__ float  g_ball[NTOT];

// ------------------------------- helpers ----------------------------------
__device__ __forceinline__ uint32_t smem_u32(const void* p){
    uint32_t a;
    asm("{ .reg .u64 t; cvta.to.shared.u64 t, %1; cvt.u32.u64 %0, t; }" : "=r"(a) : "l"(p));
    return a;
}

#define CP_ASYNC16(dst, src) \
    asm volatile("cp.async.cg.shared.global [%0], [%1], 16;" :: "r"(dst), "l"(src))
#define CP_COMMIT() asm volatile("cp.async.commit_group;" ::: "memory")
#define CP_WAIT1()  asm volatile("cp.async.wait_group 1;" ::: "memory")
#define CP_WAIT0()  asm volatile("cp.async.wait_group 0;" ::: "memory")

#define LDSM4(r, addr) \
    asm volatile("ldmatrix.sync.aligned.m8n8.x4.shared.b16 {%0,%1,%2,%3}, [%4];" \
        : "=r"((r)[0]), "=r"((r)[1]), "=r"((r)[2]), "=r"((r)[3]) : "r"(addr))

#define MMAF16(d, a, b0, b1) \
    asm volatile("mma.sync.aligned.m16n8k16.row.col.f32.f16.f16.f32 " \
        "{%0,%1,%2,%3}, {%4,%5,%6,%7}, {%8,%9}, {%0,%1,%2,%3};" \
        : "+f"((d)[0]), "+f"((d)[1]), "+f"((d)[2]), "+f"((d)[3]) \
        : "r"((a)[0]), "r"((a)[1]), "r"((a)[2]), "r"((a)[3]), "r"(b0), "r"(b1))

// ---------------------------------------------------------------------------
// Prep A: convert [h|x] -> fp16 plane, row-major [m][k]
// ---------------------------------------------------------------------------
__global__ __launch_bounds__(256)
void prep_a(const float* __restrict__ x, const float* __restrict__ h)
{
    const int id = blockIdx.x * 256 + threadIdx.x;
    const int m  = id / 544;
    const int k  = (id % 544) * 8;
    const float* src = (k < MEMD) ? h + (size_t)m * MEMD + k
                                  : x + (size_t)m * IN_DIM + (k - MEMD);
    float4 v0 = *reinterpret_cast<const float4*>(src);
    float4 v1 = *reinterpret_cast<const float4*>(src + 4);
    float vv[8] = {v0.x, v0.y, v0.z, v0.w, v1.x, v1.y, v1.z, v1.w};
    unsigned short hs[8];
    #pragma unroll
    for (int i = 0; i < 8; i++) hs[i] = __half_as_ushort(__float2half_rn(vv[i]));
    uint4 H;
    H.x = hs[0] | ((uint32_t)hs[1] << 16);  H.y = hs[2] | ((uint32_t)hs[3] << 16);
    H.z = hs[4] | ((uint32_t)hs[5] << 16);  H.w = hs[6] | ((uint32_t)hs[7] << 16);
    *reinterpret_cast<uint4*>(g_Ah + (size_t)m * KDIM + k) = H;
}

// ---------------------------------------------------------------------------
// Prep W: transpose+concat [W1|Wd|Wu] -> fp16 plane [n][k]; pack biases
// ---------------------------------------------------------------------------
__global__ void prep_w(const float* __restrict__ W1, const float* __restrict__ Wd,
                       const float* __restrict__ Wu,
                       const float* __restrict__ b1, const float* __restrict__ bd,
                       const float* __restrict__ bu)
{
    __shared__ float t[32][33];
    const int k0 = blockIdx.x * 32, n0 = blockIdx.y * 32;
    const int tx = threadIdx.x, ty = threadIdx.y;
    const float* Wsrc; int ldw, noff;
    if (n0 < 512)      { Wsrc = W1; ldw = 512; noff = 0; }
    else if (n0 < 768) { Wsrc = Wd; ldw = 256; noff = 512; }
    else               { Wsrc = Wu; ldw = 256; noff = 768; }
    #pragma unroll
    for (int i = 0; i < 4; i++)
        t[ty + 8*i][tx] = Wsrc[(size_t)(k0 + ty + 8*i) * ldw + (n0 - noff) + tx];
    __syncthreads();
    #pragma unroll
    for (int i = 0; i < 4; i++) {
        const int n = n0 + ty + 8*i;
        g_Bh[(size_t)n * KDIM + k0 + tx] = __float2half_rn(t[tx][ty + 8*i]);
    }
    if (blockIdx.x == 0 && ty == 0) {
        const int n = n0 + tx;
        const float* bsrc = (n < 512) ? b1 : (n < 768 ? bd : bu);
        const int off = (n < 512) ? 0 : (n < 768 ? 512 : 768);
        g_ball[n] = bsrc[n - off];
    }
}

// ---------------------------------------------------------------------------
// Prep W2: transpose W2[512][256] -> g_W2t[256][512] fp16
// ---------------------------------------------------------------------------
__global__ void prep_w2(const float* __restrict__ W2)
{
    __shared__ float t[32][33];
    const int k0 = blockIdx.x * 32, n0 = blockIdx.y * 32;
    const int tx = threadIdx.x, ty = threadIdx.y;
    #pragma unroll
    for (int i = 0; i < 4; i++)
        t[ty + 8*i][tx] = W2[(size_t)(k0 + ty + 8*i) * 256 + n0 + tx];
    __syncthreads();
    #pragma unroll
    for (int i = 0; i < 4; i++)
        g_W2t[(size_t)(n0 + ty + 8*i) * 512 + k0 + tx] = __float2half_rn(t[tx][ty + 8*i]);
}

// ---------------------------------------------------------------------------
// GEMM1: BM=128, BN=128, BK=64; 256 thr; 3-stage cp.async; 2 CTAs/SM.
// Warp grid 4m x 2n, warp tile 32x64 (identical per-warp microkernel).
// ---------------------------------------------------------------------------
#define ROWB     144
#define OFF_AH   0
#define OFF_BH   18432                   // 128*144
#define ST_BYTES 36864                   // (128+128)*144 = 36KB per stage
#define NSTAGE   3
#define SMEM_G1  (NSTAGE * ST_BYTES)     // 108KB -> 2 CTAs/SM
#define KSTAGES  (KDIM / 64)             // 68

__global__ __launch_bounds__(256, 2)
void gemm1_mma()
{
    extern __shared__ char smem[];
    const uint32_t sb = smem_u32(smem);
    const int tid  = threadIdx.x;
    const int wid  = tid >> 5;
    const int lane = tid & 31;
    const int bx = blockIdx.x;   // n-tile 0..7
    const int by = blockIdx.y;   // m-tile 0..63

    const __half* baseA = g_Ah + (size_t)(by * 128) * KDIM;
    const __half* baseB = g_Bh + (size_t)(bx * 128) * KDIM;

    // 2048 16B-chunks per stage (A: 1024, B: 1024), 8 per thread
    auto load_stage = [&](int s) {
        const uint32_t st = sb + (uint32_t)(s % NSTAGE) * ST_BYTES;
        const int koff = s * 64;
        #pragma unroll
        for (int t = 0; t < 8; t++) {
            const int c = t * 256 + tid;
            const __half* src;
            uint32_t dst;
            if (c < 1024) {
                const int row = c >> 3, g = c & 7;
                src = baseA + (size_t)row * KDIM + koff + g * 8;
                dst = st + OFF_AH + row * ROWB + g * 16;
            } else {
                const int c2 = c - 1024;
                const int row = c2 >> 3, g = c2 & 7;
                src = baseB + (size_t)row * KDIM + koff + g * 8;
                dst = st + OFF_BH + row * ROWB + g * 16;
            }
            CP_ASYNC16(dst, src);
        }
        CP_COMMIT();
    };

    const int wm = wid & 3;        // m-warp 0..3
    const int wn = wid >> 2;       // n-warp 0..1
    const int rsel = lane & 15;
    const int bsel = lane >> 4;

    float acc[2][8][4];
    #pragma unroll
    for (int mf = 0; mf < 2; mf++)
        #pragma unroll
        for (int nf = 0; nf < 8; nf++)
            #pragma unroll
            for (int q = 0; q < 4; q++) acc[mf][nf][q] = 0.f;

    load_stage(0);
    load_stage(1);

    #pragma unroll 1
    for (int s = 0; s < KSTAGES; s++) {
        if (s + 1 < KSTAGES) { CP_WAIT1(); } else { CP_WAIT0(); }
        __syncthreads();
        if (s + 2 < KSTAGES) load_stage(s + 2);

        const uint32_t st = sb + (uint32_t)(s % NSTAGE) * ST_BYTES;
        const uint32_t ra = st + OFF_AH + (uint32_t)(wm * 32 + rsel) * ROWB;
        const uint32_t rb = st + OFF_BH + (uint32_t)(wn * 64 + rsel) * ROWB;

        #pragma unroll
        for (int kk = 0; kk < 4; kk++) {
            const uint32_t kaddr = (uint32_t)(((kk << 1) + bsel) << 4);
            uint32_t Ah[2][4], Bh[4][4];
            #pragma unroll
            for (int mf = 0; mf < 2; mf++)
                LDSM4(Ah[mf], ra + (uint32_t)(mf * 16) * ROWB + kaddr);
            #pragma unroll
            for (int j = 0; j < 4; j++)
                LDSM4(Bh[j], rb + (uint32_t)(j * 16) * ROWB + kaddr);
            #pragma unroll
            for (int j = 0; j < 4; j++)
                #pragma unroll
                for (int mf = 0; mf < 2; mf++)
                    #pragma unroll
                    for (int pp = 0; pp < 2; pp++)
                        MMAF16(acc[mf][j * 2 + pp], Ah[mf], Bh[j][pp], Bh[j][2 + pp]);
        }
    }

    const int g  = lane >> 2;
    const int t2 = (lane & 3) * 2;
    const int ncol0 = bx * 128 + wn * 64;
    #pragma unroll
    for (int mf = 0; mf < 2; mf++) {
        const int m = by * 128 + wm * 32 + mf * 16 + g;
        float* y0 = g_Y + (size_t)m * NTOT + ncol0;
        float* y1 = y0 + (size_t)8 * NTOT;
        #pragma unroll
        for (int nf = 0; nf < 8; nf++) {
            const int nn = nf * 8 + t2;
            const float bz0 = g_ball[ncol0 + nn];
            const float bz1 = g_ball[ncol0 + nn + 1];
            *reinterpret_cast<float2*>(y0 + nn) =
                make_float2(acc[mf][nf][0] + bz0, acc[mf][nf][1] + bz1);
            *reinterpret_cast<float2*>(y1 + nn) =
                make_float2(acc[mf][nf][2] + bz0, acc[mf][nf][3] + bz1);
        }
    }
}

// ---------------------------------------------------------------------------
// fuse2_mma: LN + exact GELU -> fp16 smem; GEMM2 via HMMA; gates + renorm.
// 64 rows/block, grid 128, 256 thr. (round-14 winner, unchanged)
// ---------------------------------------------------------------------------
#define TROW    1040
#define F2_T    0
#define W2ROW   144
#define W2_ST   36864
#define F2_W2   66560
#define F2_H2   177152
#define F2_N2   177408
#define F2_SC   178432
#define SMEM_F2 178688

__global__ __launch_bounds__(256, 1)
void fuse2_mma(const float* __restrict__ h,
               const float* __restrict__ gam, const float* __restrict__ bet,
               const float* __restrict__ b2, float* __restrict__ out)
{
    extern __shared__ char smem[];
    const uint32_t sb = smem_u32(smem);
    float* s_h2 = reinterpret_cast<float*>(smem + F2_H2);
    float* s_n2 = reinterpret_cast<float*>(smem + F2_N2);
    float* s_sc = reinterpret_cast<float*>(smem + F2_SC);

    const int tid  = threadIdx.x;
    const int wid  = tid >> 5;
    const int lane = tid & 31;
    const int row0 = blockIdx.x * 64;

    auto load_w2 = [&](int s) {
        const uint32_t st = sb + F2_W2 + (uint32_t)(s % 3) * W2_ST;
        const int koff = s * 64;
        #pragma unroll
        for (int t = 0; t < 8; t++) {
            const int c = t * 256 + tid;
            const int n = c >> 3, g = c & 7;
            const __half* src = g_W2t + (size_t)n * 512 + koff + g * 8;
            CP_ASYNC16(st + n * W2ROW + g * 16, src);
        }
        CP_COMMIT();
    };
    load_w2(0);
    load_w2(1);

    // ---- Phase A: LN + GELU -> fp16 smem; per-row ||h||^2. 8 rows/warp.
    const int wrow = wid * 8;
    #pragma unroll 1
    for (int i = 0; i < 8; i++) {
        const int r = wrow + i;
        const float* yrow = g_Y + (size_t)(row0 + r) * NTOT;
        float vals[16];
        float s = 0.f, s2 = 0.f;
        #pragma unroll
        for (int q = 0; q < 4; q++) {
            float4 v = *reinterpret_cast<const float4*>(yrow + (lane + q * 32) * 4);
            vals[q*4+0] = v.x; vals[q*4+1] = v.y; vals[q*4+2] = v.z; vals[q*4+3] = v.w;
            s  += v.x + v.y + v.z + v.w;
            s2 += v.x*v.x + v.y*v.y + v.z*v.z + v.w*v.w;
        }
        #pragma unroll
        for (int o = 16; o; o >>= 1) {
            s  += __shfl_xor_sync(0xffffffffu, s,  o);
            s2 += __shfl_xor_sync(0xffffffffu, s2, o);
        }
        const float mu   = s * (1.f / 512.f);
        const float var  = s2 * (1.f / 512.f) - mu * mu;
        const float rstd = rsqrtf(var + 1e-5f);
        #pragma unroll
        for (int q = 0; q < 4; q++) {
            const int c = (lane + q * 32) * 4;
            float4 gv = *reinterpret_cast<const float4*>(gam + c);
            float4 bv = *reinterpret_cast<const float4*>(bet + c);
            float gl[4];
            float g4[4]  = {gv.x, gv.y, gv.z, gv.w};
            float be4[4] = {bv.x, bv.y, bv.z, bv.w};
            #pragma unroll
            for (int e = 0; e < 4; e++) {
                float t = (vals[q*4+e] - mu) * rstd * g4[e] + be4[e];
                gl[e] = 0.5f * t * (1.f + erff(t * 0.7071067811865475f));
            }
            uint32_t u0 = __half_as_ushort(__float2half_rn(gl[0])) |
                          ((uint32_t)__half_as_ushort(__float2half_rn(gl[1])) << 16);
            uint32_t u1 = __half_as_ushort(__float2half_rn(gl[2])) |
                          ((uint32_t)__half_as_ushort(__float2half_rn(gl[3])) << 16);
            asm volatile("st.shared.v2.b32 [%0], {%1, %2};"
                :: "r"(sb + F2_T + (uint32_t)r * TROW + (uint32_t)c * 2), "r"(u0), "r"(u1)
                : "memory");
        }
        const float* hrow = h + (size_t)(row0 + r) * MEMD;
        float4 a0 = *reinterpret_cast<const float4*>(hrow + lane * 8);
        float4 a1 = *reinterpret_cast<const float4*>(hrow + lane * 8 + 4);
        float hh = a0.x*a0.x + a0.y*a0.y + a0.z*a0.z + a0.w*a0.w
                 + a1.x*a1.x + a1.y*a1.y + a1.z*a1.z + a1.w*a1.w;
        #pragma unroll
        for (int o = 16; o; o >>= 1) hh += __shfl_xor_sync(0xffffffffu, hh, o);
        if (lane == 0) s_h2[r] = hh;
    }

    // ---- Phase B: MMA GEMM2 (64x256x512), warp grid 2m x 4n
    const int wm = wid >> 2;
    const int wn = wid & 3;
    const int rsel = lane & 15;
    const int bsel = lane >> 4;

    float acc[2][8][4];
    #pragma unroll
    for (int mf = 0; mf < 2; mf++)
        #pragma unroll
        for (int nf = 0; nf < 8; nf++)
            #pragma unroll
            for (int q = 0; q < 4; q++) acc[mf][nf][q] = 0.f;

    #pragma unroll 1
    for (int s = 0; s < 8; s++) {
        if (s < 7) { CP_WAIT1(); } else { CP_WAIT0(); }
        __syncthreads();
        if (s + 2 < 8) load_w2(s + 2);

        const uint32_t stw = sb + F2_W2 + (uint32_t)(s % 3) * W2_ST;
        const uint32_t ta  = sb + F2_T + (uint32_t)(s * 128) + (uint32_t)(wm * 32 + rsel) * TROW;
        const uint32_t rb  = stw + (uint32_t)(wn * 64 + rsel) * W2ROW;

        #pragma unroll
        for (int kk = 0; kk < 4; kk++) {
            const uint32_t kaddr = (uint32_t)(((kk << 1) + bsel) << 4);
            uint32_t Ah[2][4], Bh[4][4];
            #pragma unroll
            for (int mf = 0; mf < 2; mf++)
                LDSM4(Ah[mf], ta + (uint32_t)(mf * 16) * TROW + kaddr);
            #pragma unroll
            for (int j = 0; j < 4; j++)
                LDSM4(Bh[j], rb + (uint32_t)(j * 16) * W2ROW + kaddr);
            #pragma unroll
            for (int j = 0; j < 4; j++)
                #pragma unroll
                for (int mf = 0; mf < 2; mf++)
                    #pragma unroll
                    for (int pp = 0; pp < 2; pp++)
                        MMAF16(acc[mf][j * 2 + pp], Ah[mf], Bh[j][pp], Bh[j][2 + pp]);
        }
    }

    // ---- Phase C: gates + liquid update + renorm
    const int g  = lane >> 2;
    const int t2 = (lane & 3) * 2;
    float nh2[2][2] = {{0.f, 0.f}, {0.f, 0.f}};

    #pragma unroll
    for (int mf = 0; mf < 2; mf++) {
        const int r1 = wm * 32 + mf * 16 + g;
        const int rg1 = row0 + r1, rg2 = rg1 + 8;
        const float* y1 = g_Y + (size_t)rg1 * NTOT;
        const float* y2 = g_Y + (size_t)rg2 * NTOT;
        const float* h1 = h + (size_t)rg1 * MEMD;
        const float* h2p = h + (size_t)rg2 * MEMD;
        #pragma unroll
        for (int nf = 0; nf < 8; nf++) {
            const int j0 = wn * 64 + nf * 8 + t2;
            const float bz0 = b2[j0], bz1 = b2[j0 + 1];
            float2 d1 = *reinterpret_cast<const float2*>(y1 + 512 + j0);
            float2 u1 = *reinterpret_cast<const float2*>(y1 + 768 + j0);
            float2 d2 = *reinterpret_cast<const float2*>(y2 + 512 + j0);
            float2 u2 = *reinterpret_cast<const float2*>(y2 + 768 + j0);
            float2 hv1 = *reinterpret_cast<const float2*>(h1 + j0);
            float2 hv2 = *reinterpret_cast<const float2*>(h2p + j0);

            float hc, dec, ts, uu, nh;
            hc = tanhf(acc[mf][nf][0] + bz0);
            dec = 1.f / (1.f + __expf(-d1.x)); ts = 0.1f + 9.9f * dec + 1e-6f;
            uu  = 1.f / (1.f + __expf(-u1.x));
            nh = (1.f - uu) * (hv1.x / ts) + uu * hc;
            acc[mf][nf][0] = nh; nh2[mf][0] += nh * nh;

            hc = tanhf(acc[mf][nf][1] + bz1);
            dec = 1.f / (1.f + __expf(-d1.y)); ts = 0.1f + 9.9f * dec + 1e-6f;
            uu  = 1.f / (1.f + __expf(-u1.y));
            nh = (1.f - uu) * (hv1.y / ts) + uu * hc;
            acc[mf][nf][1] = nh; nh2[mf][0] += nh * nh;

            hc = tanhf(acc[mf][nf][2] + bz0);
            dec = 1.f / (1.f + __expf(-d2.x)); ts = 0.1f + 9.9f * dec + 1e-6f;
            uu  = 1.f / (1.f + __expf(-u2.x));
            nh = (1.f - uu) * (hv2.x / ts) + uu * hc;
            acc[mf][nf][2] = nh; nh2[mf][1] += nh * nh;

            hc = tanhf(acc[mf][nf][3] + bz1);
            dec = 1.f / (1.f + __expf(-d2.y)); ts = 0.1f + 9.9f * dec + 1e-6f;
            uu  = 1.f / (1.f + __expf(-u2.y));
            nh = (1.f - uu) * (hv2.y / ts) + uu * hc;
            acc[mf][nf][3] = nh; nh2[mf][1] += nh * nh;
        }
    }

    #pragma unroll
    for (int mf = 0; mf < 2; mf++)
        #pragma unroll
        for (int hh = 0; hh < 2; hh++) {
            float v = nh2[mf][hh];
            v += __shfl_xor_sync(0xffffffffu, v, 1);
            v += __shfl_xor_sync(0xffffffffu, v, 2);
            if ((lane & 3) == 0)
                s_n2[(wm * 32 + mf * 16 + g + hh * 8) * 4 + wn] = v;
        }
    __syncthreads();

    if (tid < 64) {
        float n2 = s_n2[tid * 4 + 0] + s_n2[tid * 4 + 1]
                 + s_n2[tid * 4 + 2] + s_n2[tid * 4 + 3];
        s_sc[tid] = fmaxf(sqrtf(s_h2[tid]), 1e-6f) / fmaxf(sqrtf(n2), 1e-12f);
    }
    __syncthreads();

    #pragma unroll
    for (int mf = 0; mf < 2; mf++) {
        const int r1 = wm * 32 + mf * 16 + g;
        const float sc1 = s_sc[r1], sc2 = s_sc[r1 + 8];
        float* o1 = out + (size_t)(row0 + r1) * MEMD;
        float* o2 = out + (size_t)(row0 + r1 + 8) * MEMD;
        #pragma unroll
        for (int nf = 0; nf < 8; nf++) {
            const int j0 = wn * 64 + nf * 8 + t2;
            *reinterpret_cast<float2*>(o1 + j0) =
                make_float2(acc[mf][nf][0] * sc1, acc[mf][nf][1] * sc1);
            *reinterpret_cast<float2*>(o2 + j0) =
                make_float2(acc[mf][nf][2] * sc2, acc[mf][nf][3] * sc2);
        }
    }
}

// ---------------------------------------------------------------------------
extern "C" void kernel_launch(void* const* d_in, const int* in_sizes, int n_in,
                              void* d_out, int out_size)
{
    (void)in_sizes; (void)n_in; (void)out_size;
    const float* x   = (const float*)d_in[0];
    const float* h   = (const float*)d_in[1];
    const float* W1  = (const float*)d_in[2];
    const float* b1  = (const float*)d_in[3];
    const float* gam = (const float*)d_in[4];
    const float* bet = (const float*)d_in[5];
    const float* W2  = (const float*)d_in[6];
    const float* b2  = (const float*)d_in[7];
    const float* Wd  = (const float*)d_in[8];
    const float* bd  = (const float*)d_in[9];
    const float* Wu  = (const float*)d_in[10];
    const float* bu  = (const float*)d_in[11];
    float* out = (float*)d_out;

    cudaFuncSetAttribute(gemm1_mma, cudaFuncAttributeMaxDynamicSharedMemorySize, SMEM_G1);
    cudaFuncSetAttribute(fuse2_mma, cudaFuncAttributeMaxDynamicSharedMemorySize, SMEM_F2);

    prep_a<<<(BATCH * (KDIM / 8)) / 256, 256>>>(x, h);
    prep_w<<<dim3(KDIM / 32, NTOT / 32), dim3(32, 8)>>>(W1, Wd, Wu, b1, bd, bu);
    prep_w2<<<dim3(16, 8), dim3(32, 8)>>>(W2);

    dim3 ggrid(NTOT / 128, BATCH / 128);   // 8 x 64 = 512 CTAs, 2/SM
    gemm1_mma<<<ggrid, 256, SMEM_G1>>>();

    fuse2_mma<<<BATCH / 64, 256, SMEM_F2>>>(h, gam, bet, b2, out);
}